// round 13
// baseline (speedup 1.0000x reference)
#include <cuda_runtime.h>
#include <cstdint>

typedef unsigned int u32;
typedef unsigned long long u64;

#define BBATCH 2048
#define SSEQ 256
#define NTOK 6
#define STARTTOK 4
#define NT 128

#define RECONS_N (BBATCH*SSEQ*4)
#define TOKOFF RECONS_N
#define MUOFF (RECONS_N + BBATCH*SSEQ)
#define LVOFF (MUOFF + BBATCH*3)
#define FULLN (LVOFF + BBATCH*3)

// SMEM float offsets (common)
#define O_W1A 0        /* [d][P][4] = wir0,wir1,whr0,whr1 : 8192 */
#define O_W1B 8192     /* [d][P][4] = wiz0,wiz1,whz0,whz1 : 8192 */
#define O_W1C 16384    /* [d][P][4] = win0,win1,whn0,whn1 : 8192 */
#define O_W0A 24576    /* [d][P][4] = wr0,wr1,wz0,wz1 : 8192 */
#define O_W0B 32768    /* [d][P][2] = wn0,wn1 : 4096 */
#define O_TAB 36864    /* [t][P][8] = r0,r1,z0,z1,n0,n1,p,p : 1536 */
#define O_B0  38400
#define O_BI1 38592
#define O_BH1 38784
#define O_H0B 38976    /* [2][64][40] : 5120 */
#define O_H1B 44096    /* [2][64][40] : 5120 */
#define HBUF  2560     /* floats per single buffer */
// encoder-only
#define O_MUW 49216
#define O_VARW 49408
#define O_MUB 49600
#define O_VARB 49604
#define O_PRJW 49608
#define O_PRJB 49800
#define O_ZS  49864
#define ENC_F 49912
// decoder-only
#define O_HW  49216
#define O_HB2 49472
#define O_K0  49476
#define O_K1  49732
#define O_TOKD 49988
#define O_LSTG 50004   /* [4w*4v][16rows] */
#define DEC_F 50260

__device__ float g_hz[BBATCH*64];

// ---------- f32x2 helpers ----------
__device__ __forceinline__ void upk2(u64 v, float& a, float& b){
    asm("mov.b64 {%0,%1},%2;" : "=f"(a), "=f"(b) : "l"(v));
}
__device__ __forceinline__ u64 pack2(float x, float y){
    u64 r; asm("mov.b64 %0,{%1,%2};" : "=l"(r) : "f"(x), "f"(y)); return r;
}
__device__ __forceinline__ u64 ff2(u64 a, u64 b, u64 c){
    u64 d; asm("fma.rn.f32x2 %0,%1,%2,%3;" : "=l"(d) : "l"(a), "l"(b), "l"(c)); return d;
}
__device__ __forceinline__ u64 add2(u64 a, u64 b){
    u64 c; asm("add.rn.f32x2 %0,%1,%2;" : "=l"(c) : "l"(a), "l"(b)); return c;
}
__device__ __forceinline__ u64 d2u(double d){ return (u64)__double_as_longlong(d); }

// ---------- threefry2x32-20 (exact JAX) ----------
__device__ __forceinline__ void threefry(u32 k0, u32 k1, u32 x0, u32 x1, u32& o0, u32& o1){
    u32 ks2 = k0 ^ k1 ^ 0x1BD11BDAu;
    x0 += k0; x1 += k1;
#define TFR(r) { x0 += x1; x1 = __funnelshift_l(x1, x1, (r)); x1 ^= x0; }
    TFR(13) TFR(15) TFR(26) TFR(6)   x0 += k1;  x1 += ks2 + 1u;
    TFR(17) TFR(29) TFR(16) TFR(24)  x0 += ks2; x1 += k0 + 2u;
    TFR(13) TFR(15) TFR(26) TFR(6)   x0 += k0;  x1 += k1 + 3u;
    TFR(17) TFR(29) TFR(16) TFR(24)  x0 += k1;  x1 += ks2 + 4u;
    TFR(13) TFR(15) TFR(26) TFR(6)   x0 += ks2; x1 += k0 + 5u;
#undef TFR
    o0 = x0; o1 = x1;
}
__device__ __forceinline__ u32 tf_bits32(u32 k0, u32 k1, u32 i){
    u32 a, b; threefry(k0, k1, 0u, i, a, b); return a ^ b;
}
__device__ __forceinline__ float bits2f(u32 b){
    return __uint_as_float((b >> 9) | 0x3f800000u) - 1.0f;
}
__device__ __forceinline__ float sigf(float x){ return 0.5f + 0.5f * tanhf(0.5f * x); }

__device__ __forceinline__ float erfinv_f(float x){
    float w = -log1pf(-x * x), p;
    if (w < 5.f){
        w -= 2.5f;
        p = 2.81022636e-08f;
        p = fmaf(p, w, 3.43273939e-07f);
        p = fmaf(p, w, -3.5233877e-06f);
        p = fmaf(p, w, -4.39150654e-06f);
        p = fmaf(p, w, 0.00021858087f);
        p = fmaf(p, w, -0.00125372503f);
        p = fmaf(p, w, -0.00417768164f);
        p = fmaf(p, w, 0.246640727f);
        p = fmaf(p, w, 1.50140941f);
    } else {
        w = sqrtf(w) - 3.f;
        p = -0.000200214257f;
        p = fmaf(p, w, 0.000100950558f);
        p = fmaf(p, w, 0.00134934322f);
        p = fmaf(p, w, -0.00367342844f);
        p = fmaf(p, w, 0.00573950773f);
        p = fmaf(p, w, -0.0076224613f);
        p = fmaf(p, w, 0.00943887047f);
        p = fmaf(p, w, 1.00167406f);
        p = fmaf(p, w, 2.83297682f);
    }
    return p * x;
}

// ---------- per-lane bias bundle ----------
struct Biases {
    float b0r0,b0r1,b0z0,b0z1,b0n0,b0n1;
    float i1r0,i1r1,i1z0,i1z1,i1n0,i1n1;
    float h1r0,h1r1,h1z0,h1z1,h1n0,h1n1;
};

// ---------- matvecs: lane owns unit-pair P, 4 rows (4rq..4rq+3) ----------
// w pointers pre-offset by P; h pointers pre-offset by 8*rq.
__device__ __forceinline__ void l0mv(const float* xc, const float* w0a, const float* w0b,
                                     u64 ar[4], u64 az[4], u64 an[4]){
    ar[0]=ar[1]=ar[2]=ar[3]=az[0]=az[1]=az[2]=az[3]=an[0]=an[1]=an[2]=an[3]=0ull;
#pragma unroll 8
    for (int d = 0; d < 64; d++){
        double2 wa = *(const double2*)(w0a + d * 128);
        double  wb = *(const double*)(w0b + d * 64);
        u64 WR = d2u(wa.x), WZ = d2u(wa.y), WN = d2u(wb);
        double2 XA = *(const double2*)(xc + d * 40);
        double2 XB = *(const double2*)(xc + d * 40 + 4);
        u64 x[4] = { d2u(XA.x), d2u(XA.y), d2u(XB.x), d2u(XB.y) };
#pragma unroll
        for (int k = 0; k < 4; k++){
            ar[k] = ff2(x[k], WR, ar[k]);
            az[k] = ff2(x[k], WZ, az[k]);
            an[k] = ff2(x[k], WN, an[k]);
        }
    }
}

__device__ __forceinline__ void l1mv(const float* xc, const float* hc,
                                     const float* w1a, const float* w1b, const float* w1c,
                                     u64 pr[4], u64 pz[4], u64 pin[4], u64 phn[4]){
#pragma unroll
    for (int k = 0; k < 4; k++){ pr[k]=pz[k]=pin[k]=phn[k]=0ull; }
#pragma unroll 8
    for (int d = 0; d < 64; d++){
        double2 wa = *(const double2*)(w1a + d * 128);
        double2 wb = *(const double2*)(w1b + d * 128);
        double2 wc = *(const double2*)(w1c + d * 128);
        u64 WIR = d2u(wa.x), WHR = d2u(wa.y);
        u64 WIZ = d2u(wb.x), WHZ = d2u(wb.y);
        u64 WIN = d2u(wc.x), WHN = d2u(wc.y);
        double2 XA = *(const double2*)(xc + d * 40);
        double2 XB = *(const double2*)(xc + d * 40 + 4);
        double2 HA = *(const double2*)(hc + d * 40);
        double2 HB = *(const double2*)(hc + d * 40 + 4);
        u64 x[4] = { d2u(XA.x), d2u(XA.y), d2u(XB.x), d2u(XB.y) };
        u64 h[4] = { d2u(HA.x), d2u(HA.y), d2u(HB.x), d2u(HB.y) };
#pragma unroll
        for (int k = 0; k < 4; k++){
            pr[k]  = ff2(x[k], WIR, ff2(h[k], WHR, pr[k]));
            pz[k]  = ff2(x[k], WIZ, ff2(h[k], WHZ, pz[k]));
            pin[k] = ff2(x[k], WIN, pin[k]);
            phn[k] = ff2(h[k], WHN, phn[k]);
        }
    }
}

// L0 epilogue. h0n = destination buffer base (sm + O_H0B + nb*HBUF); writes dup'd h.
__device__ __forceinline__ void l0epi(const float* sm, float* h0n, int P, int rq,
                                      const int* tk, const u64 ar[4], const u64 az[4],
                                      const u64 an[4], const Biases& B,
                                      float* hp0x, float* hp0y){
#pragma unroll
    for (int k = 0; k < 4; k++){
        const float* tb = sm + O_TAB + (tk[k] * 32 + P) * 8;
        float4 tA = *(const float4*)tb;
        float4 tB = *(const float4*)(tb + 4);
        float a0, a1, z0, z1, n0, n1;
        upk2(ar[k], a0, a1); upk2(az[k], z0, z1); upk2(an[k], n0, n1);
        float rx = sigf(tA.x + a0 + B.b0r0);
        float ry = sigf(tA.y + a1 + B.b0r1);
        float zx = sigf(tA.z + z0 + B.b0z0);
        float zy = sigf(tA.w + z1 + B.b0z1);
        float nx = tanhf(tB.x + rx * (n0 + B.b0n0));
        float ny = tanhf(tB.y + ry * (n1 + B.b0n1));
        hp0x[k] = (1.f - zx) * nx + zx * hp0x[k];
        hp0y[k] = (1.f - zy) * ny + zy * hp0y[k];
    }
    float* o0 = h0n + (2 * P) * 40 + 8 * rq;
    float* o1 = o0 + 40;
    *(float4*)(o0)     = make_float4(hp0x[0], hp0x[0], hp0x[1], hp0x[1]);
    *(float4*)(o0 + 4) = make_float4(hp0x[2], hp0x[2], hp0x[3], hp0x[3]);
    *(float4*)(o1)     = make_float4(hp0y[0], hp0y[0], hp0y[1], hp0y[1]);
    *(float4*)(o1 + 4) = make_float4(hp0y[2], hp0y[2], hp0y[3], hp0y[3]);
}

__device__ __forceinline__ void l1epi(float* h1n, int P, int rq,
                                      const u64 pr[4], const u64 pz[4],
                                      const u64 pin[4], const u64 phn[4],
                                      const Biases& B, float* hp1x, float* hp1y){
#pragma unroll
    for (int k = 0; k < 4; k++){
        float r0, r1, z0, z1, i0, i1, g0, g1;
        upk2(pr[k], r0, r1); upk2(pz[k], z0, z1);
        upk2(pin[k], i0, i1); upk2(phn[k], g0, g1);
        float rx = sigf(r0 + B.i1r0 + B.h1r0);
        float ry = sigf(r1 + B.i1r1 + B.h1r1);
        float zx = sigf(z0 + B.i1z0 + B.h1z0);
        float zy = sigf(z1 + B.i1z1 + B.h1z1);
        float nx = tanhf(i0 + B.i1n0 + rx * (g0 + B.h1n0));
        float ny = tanhf(i1 + B.i1n1 + ry * (g1 + B.h1n1));
        hp1x[k] = (1.f - zx) * nx + zx * hp1x[k];
        hp1y[k] = (1.f - zy) * ny + zy * hp1y[k];
    }
    float* o0 = h1n + (2 * P) * 40 + 8 * rq;
    float* o1 = o0 + 40;
    *(float4*)(o0)     = make_float4(hp1x[0], hp1x[0], hp1x[1], hp1x[1]);
    *(float4*)(o0 + 4) = make_float4(hp1x[2], hp1x[2], hp1x[3], hp1x[3]);
    *(float4*)(o1)     = make_float4(hp1y[0], hp1y[0], hp1y[1], hp1y[1]);
    *(float4*)(o1 + 4) = make_float4(hp1y[2], hp1y[2], hp1y[3], hp1y[3]);
}

// ---------- weight staging (pair-packed layouts) ----------
__device__ __forceinline__ void stage_weights(float* sm, int tid,
    const float* Whh0, const float* Wih1, const float* Whh1,
    const float* bhh0, const float* bih1, const float* bhh1){
    for (int i = tid; i < 2048; i += NT){
        int d = i >> 5, P = i & 31;
        int u0 = 2 * P, u1 = 2 * P + 1;
        *(float4*)(sm + O_W1A + i * 4) = make_float4(
            Wih1[u0*64+d], Wih1[u1*64+d], Whh1[u0*64+d], Whh1[u1*64+d]);
        *(float4*)(sm + O_W1B + i * 4) = make_float4(
            Wih1[(64+u0)*64+d], Wih1[(64+u1)*64+d], Whh1[(64+u0)*64+d], Whh1[(64+u1)*64+d]);
        *(float4*)(sm + O_W1C + i * 4) = make_float4(
            Wih1[(128+u0)*64+d], Wih1[(128+u1)*64+d], Whh1[(128+u0)*64+d], Whh1[(128+u1)*64+d]);
        *(float4*)(sm + O_W0A + i * 4) = make_float4(
            Whh0[u0*64+d], Whh0[u1*64+d], Whh0[(64+u0)*64+d], Whh0[(64+u1)*64+d]);
        *(float2*)(sm + O_W0B + i * 2) = make_float2(
            Whh0[(128+u0)*64+d], Whh0[(128+u1)*64+d]);
    }
    for (int i = tid; i < 192; i += NT){
        sm[O_B0 + i] = bhh0[i];
        sm[O_BI1 + i] = bih1[i];
        sm[O_BH1 + i] = bhh1[i];
    }
}

__device__ __forceinline__ Biases load_biases(const float* sm, int P){
    int u0 = 2 * P, u1 = u0 + 1;
    Biases B;
    B.b0r0 = sm[O_B0+u0];      B.b0r1 = sm[O_B0+u1];
    B.b0z0 = sm[O_B0+64+u0];   B.b0z1 = sm[O_B0+64+u1];
    B.b0n0 = sm[O_B0+128+u0];  B.b0n1 = sm[O_B0+128+u1];
    B.i1r0 = sm[O_BI1+u0];     B.i1r1 = sm[O_BI1+u1];
    B.i1z0 = sm[O_BI1+64+u0];  B.i1z1 = sm[O_BI1+64+u1];
    B.i1n0 = sm[O_BI1+128+u0]; B.i1n1 = sm[O_BI1+128+u1];
    B.h1r0 = sm[O_BH1+u0];     B.h1r1 = sm[O_BH1+u1];
    B.h1z0 = sm[O_BH1+64+u0];  B.h1z1 = sm[O_BH1+64+u1];
    B.h1n0 = sm[O_BH1+128+u0]; B.h1n1 = sm[O_BH1+128+u1];
    return B;
}

// =========================== ENCODER ===========================
__global__ void __launch_bounds__(NT, 1) enc_k(
    const int* __restrict__ tokens, const float* __restrict__ emb,
    const float* __restrict__ Wih0, const float* __restrict__ Whh0,
    const float* __restrict__ bih0, const float* __restrict__ bhh0,
    const float* __restrict__ Wih1, const float* __restrict__ Whh1,
    const float* __restrict__ bih1, const float* __restrict__ bhh1,
    const float* __restrict__ muW, const float* __restrict__ mub,
    const float* __restrict__ varW, const float* __restrict__ varb,
    const float* __restrict__ prjW, const float* __restrict__ prjb,
    float* __restrict__ out, int wr_extra)
{
    extern __shared__ float sm[];
    int tid = threadIdx.x;
    stage_weights(sm, tid, Whh0, Wih1, Whh1, bhh0, bih1, bhh1);
    // token-gate table, pair-packed
    for (int i = tid; i < NTOK * 32; i += NT){
        int t = i >> 5, P = i & 31;
        int u0 = 2 * P, u1 = u0 + 1;
        float g[6];
#pragma unroll
        for (int gi = 0; gi < 3; gi++){
            float s0 = bih0[gi*64+u0], s1 = bih0[gi*64+u1];
#pragma unroll
            for (int e = 0; e < 8; e++){
                s0 = fmaf(emb[t*8+e], Wih0[(gi*64+u0)*8+e], s0);
                s1 = fmaf(emb[t*8+e], Wih0[(gi*64+u1)*8+e], s1);
            }
            g[gi*2] = s0; g[gi*2+1] = s1;
        }
        *(float4*)(sm + O_TAB + i * 8)     = make_float4(g[0], g[1], g[2], g[3]);
        *(float4*)(sm + O_TAB + i * 8 + 4) = make_float4(g[4], g[5], 0.f, 0.f);
    }
    for (int i = tid; i < 192; i += NT){
        sm[O_MUW + i] = muW[i]; sm[O_VARW + i] = varW[i]; sm[O_PRJW + i] = prjW[i];
    }
    if (tid < 3){ sm[O_MUB + tid] = mub[tid]; sm[O_VARB + tid] = varb[tid]; }
    for (int i = tid; i < 64; i += NT) sm[O_PRJB + i] = prjb[i];
    int base = blockIdx.x * 16;
    for (int i = tid; i < 2 * HBUF; i += NT){ sm[O_H0B + i] = 0.f; sm[O_H1B + i] = 0.f; }
    __syncthreads();

    int warp = tid >> 5, lane = tid & 31;
    int up = lane & 7, rq = lane >> 3;
    int P = warp * 8 + up;
    const float* w0a = sm + O_W0A + P * 4;
    const float* w0b = sm + O_W0B + P * 2;
    const float* w1a = sm + O_W1A + P * 4;
    const float* w1b = sm + O_W1B + P * 4;
    const float* w1c = sm + O_W1C + P * 4;
    Biases B = load_biases(sm, P);

    float hp0x[4], hp0y[4], hp1x[4], hp1y[4];
#pragma unroll
    for (int k = 0; k < 4; k++){ hp0x[k] = hp0y[k] = hp1x[k] = hp1y[k] = 0.f; }

    const int* tokrow = tokens + (size_t)(base + 4 * rq) * 256;

    for (int s = 0; s < 256; s++){
        int cb = s & 1, nb = cb ^ 1;
        int tk[4];
#pragma unroll
        for (int j = 0; j < 4; j++) tk[j] = tokrow[j * 256 + s];
        u64 ar[4], az[4], an[4];
        l0mv(sm + O_H0B + cb * HBUF + 8 * rq, w0a, w0b, ar, az, an);
        l0epi(sm, sm + O_H0B + nb * HBUF, P, rq, tk, ar, az, an, B, hp0x, hp0y);
        __syncthreads();
        u64 pr[4], pz[4], pin[4], phn[4];
        l1mv(sm + O_H0B + nb * HBUF + 8 * rq, sm + O_H1B + cb * HBUF + 8 * rq,
             w1a, w1b, w1c, pr, pz, pin, phn);
        l1epi(sm + O_H1B + nb * HBUF, P, rq, pr, pz, pin, phn, B, hp1x, hp1y);
    }
    __syncthreads();

    // final h1 in H1B buffer 0 (dup'd: one copy at +2r)
    if (lane < 12){
        int r = lane / 3, j = lane % 3;
        int lr = warp * 4 + r;
        int row = base + lr;
        float m = sm[O_MUB + j], v = sm[O_VARB + j];
        for (int d = 0; d < 64; d++){
            float h = sm[O_H1B + d * 40 + 2 * lr];
            m = fmaf(h, sm[O_MUW + j * 64 + d], m);
            v = fmaf(h, sm[O_VARW + j * 64 + d], v);
        }
        u32 bits = tf_bits32(0u, 1u, (u32)(row * 3 + j));
        float f01 = bits2f(bits);
        const float LO = -0.99999994f;
        float u = fmaxf(LO, fmaf(f01, 2.0f, LO));
        float eps = 1.41421356f * erfinv_f(u);
        float z = fmaf(eps, expf(0.5f * v), m);
        sm[O_ZS + lr * 3 + j] = z;
        if (wr_extra){ out[MUOFF + row * 3 + j] = m; out[LVOFF + row * 3 + j] = v; }
    }
    __syncthreads();
    for (int i = tid; i < 1024; i += NT){
        int r = i >> 6, d = i & 63;
        float z0 = sm[O_ZS + r * 3];
        float z1 = sm[O_ZS + r * 3 + 1];
        float z2 = sm[O_ZS + r * 3 + 2];
        float hx = sm[O_PRJB + d] + z0 * sm[O_PRJW + d * 3] + z1 * sm[O_PRJW + d * 3 + 1]
                 + z2 * sm[O_PRJW + d * 3 + 2];
        g_hz[(base + r) * 64 + d] = hx;
    }
}

// =========================== DECODER ===========================
__global__ void __launch_bounds__(NT, 1) dec_k(
    const float* __restrict__ dec_emb,
    const float* __restrict__ Wih0, const float* __restrict__ Whh0,
    const float* __restrict__ bih0, const float* __restrict__ bhh0,
    const float* __restrict__ Wih1, const float* __restrict__ Whh1,
    const float* __restrict__ bih1, const float* __restrict__ bhh1,
    const float* __restrict__ headW, const float* __restrict__ headb,
    float* __restrict__ out)
{
    extern __shared__ float sm[];
    int tid = threadIdx.x;
    stage_weights(sm, tid, Whh0, Wih1, Whh1, bhh0, bih1, bhh1);
    for (int i = tid; i < NTOK * 32; i += NT){
        int t = i >> 5, P = i & 31;
        int u0 = 2 * P, u1 = u0 + 1;
        float g[6];
#pragma unroll
        for (int gi = 0; gi < 3; gi++){
            float s0 = bih0[gi*64+u0], s1 = bih0[gi*64+u1];
            for (int d = 0; d < 64; d++){
                s0 = fmaf(dec_emb[t*64+d], Wih0[(gi*64+u0)*64+d], s0);
                s1 = fmaf(dec_emb[t*64+d], Wih0[(gi*64+u1)*64+d], s1);
            }
            g[gi*2] = s0; g[gi*2+1] = s1;
        }
        *(float4*)(sm + O_TAB + i * 8)     = make_float4(g[0], g[1], g[2], g[3]);
        *(float4*)(sm + O_TAB + i * 8 + 4) = make_float4(g[4], g[5], 0.f, 0.f);
    }
    for (int i = tid; i < 256; i += NT) sm[O_HW + i] = headW[i];
    if (tid < 4) sm[O_HB2 + tid] = headb[tid];
    u32* K0 = (u32*)(sm + O_K0);
    u32* K1 = (u32*)(sm + O_K1);
    for (int i = tid; i < 256; i += NT){
        u32 a, b; threefry(0u, 2u, 0u, (u32)i, a, b);
        K0[i] = a; K1[i] = b;
    }
    int* tokD = (int*)(sm + O_TOKD);
    if (tid < 16) tokD[tid] = STARTTOK;
    int base = blockIdx.x * 16;
    for (int i = tid; i < 1024; i += NT){
        int r = i >> 6, d = i & 63;
        float v = g_hz[(base + r) * 64 + d];
        sm[O_H0B + d * 40 + 2 * r] = v;  sm[O_H0B + d * 40 + 2 * r + 1] = v;
        sm[O_H1B + d * 40 + 2 * r] = v;  sm[O_H1B + d * 40 + 2 * r + 1] = v;
    }
    __syncthreads();

    int warp = tid >> 5, lane = tid & 31;
    int up = lane & 7, rq = lane >> 3;
    int P = warp * 8 + up;
    int u0 = 2 * P, u1 = u0 + 1;
    const float* w0a = sm + O_W0A + P * 4;
    const float* w0b = sm + O_W0B + P * 2;
    const float* w1a = sm + O_W1A + P * 4;
    const float* w1b = sm + O_W1B + P * 4;
    const float* w1c = sm + O_W1C + P * 4;
    Biases B = load_biases(sm, P);
    u64 WV[4];
#pragma unroll
    for (int v = 0; v < 4; v++)
        WV[v] = pack2(sm[O_HW + v * 64 + u0], sm[O_HW + v * 64 + u1]);

    float hp0x[4], hp0y[4], hp1x[4], hp1y[4];
#pragma unroll
    for (int k = 0; k < 4; k++){
        int r = 4 * rq + k;
        hp0x[k] = hp1x[k] = sm[O_H0B + u0 * 40 + 2 * r];
        hp0y[k] = hp1y[k] = sm[O_H0B + u1 * 40 + 2 * r];
    }

    const float TINYF = 1.17549435e-38f;
    for (int s = 0; s < 256; s++){
        int cb = s & 1, nb = cb ^ 1;
        u64 ar[4], az[4], an[4];
        l0mv(sm + O_H0B + cb * HBUF + 8 * rq, w0a, w0b, ar, az, an);
        __syncthreads();   // SYNC_A: prev-step token writes visible
        int tk[4];
#pragma unroll
        for (int j = 0; j < 4; j++) tk[j] = tokD[4 * rq + j];
        l0epi(sm, sm + O_H0B + nb * HBUF, P, rq, tk, ar, az, an, B, hp0x, hp0y);
        __syncthreads();   // SYNC_B: new h0 visible
        u64 pr[4], pz[4], pin[4], phn[4];
        l1mv(sm + O_H0B + nb * HBUF + 8 * rq, sm + O_H1B + cb * HBUF + 8 * rq,
             w1a, w1b, w1c, pr, pz, pin, phn);
        l1epi(sm + O_H1B + nb * HBUF, P, rq, pr, pz, pin, phn, B, hp1x, hp1y);

        // head partials: per (row k, vocab v), f32x2 over the lane's unit pair
        u64 pp[16];
#pragma unroll
        for (int k = 0; k < 4; k++){
            u64 hp = pack2(hp1x[k], hp1y[k]);
#pragma unroll
            for (int v = 0; v < 4; v++) pp[k * 4 + v] = ff2(hp, WV[v], 0ull);
        }
        // butterfly over the 8 unit-pairs (masks 1,2,4 stay within rq group)
#pragma unroll
        for (int m = 1; m < 8; m <<= 1){
#pragma unroll
            for (int j = 0; j < 16; j++){
                double o = __shfl_xor_sync(0xffffffffu,
                                           __longlong_as_double((long long)pp[j]), m);
                pp[j] = add2(pp[j], d2u(o));
            }
        }
        if (up == 0){
#pragma unroll
            for (int k = 0; k < 4; k++)
#pragma unroll
                for (int v = 0; v < 4; v++){
                    float a, b; upk2(pp[k * 4 + v], a, b);
                    sm[O_LSTG + (warp * 4 + v) * 16 + 4 * rq + k] = a + b;
                }
        }
        __syncthreads();   // SYNC_C: LSTG + h1 writes visible

        // sample: warp handles its 4 rows (lanes 0..15)
        {
            int k = lane & 15, r = k >> 2, v = k & 3;
            int lr = warp * 4 + r;
            int row = base + lr;
            float sum = ((sm[O_LSTG + v * 16 + lr] + sm[O_LSTG + (4 + v) * 16 + lr])
                         + sm[O_LSTG + (8 + v) * 16 + lr]) + sm[O_LSTG + (12 + v) * 16 + lr];
            float logit = sum + sm[O_HB2 + v];
            u32 bits = tf_bits32(K0[s], K1[s], (u32)(row * 4 + v));
            float f01 = bits2f(bits);
            float u = fmaxf(TINYF, f01 + TINYF);
            float g = -logf(-logf(u));
            float y = logit + g;
            float mx = logit;
            mx = fmaxf(mx, __shfl_xor_sync(0xffffffffu, mx, 1));
            mx = fmaxf(mx, __shfl_xor_sync(0xffffffffu, mx, 2));
            float e = expf(logit - mx);
            float den = e;
            den += __shfl_xor_sync(0xffffffffu, den, 1);
            den += __shfl_xor_sync(0xffffffffu, den, 2);
            if (lane < 16) out[((size_t)row * 256 + s) * 4 + v] = e / den;
            float by = y; int bi = v;
            { float oy = __shfl_xor_sync(0xffffffffu, by, 1);
              int   oi = __shfl_xor_sync(0xffffffffu, bi, 1);
              if (oy > by || (oy == by && oi < bi)){ by = oy; bi = oi; } }
            { float oy = __shfl_xor_sync(0xffffffffu, by, 2);
              int   oi = __shfl_xor_sync(0xffffffffu, bi, 2);
              if (oy > by || (oy == by && oi < bi)){ by = oy; bi = oi; } }
            if (lane < 16 && v == 0) tokD[lr] = bi;
        }
    }
}

__global__ void tok_cast_k(const int* __restrict__ tokens, float* __restrict__ dst){
    int i = blockIdx.x * blockDim.x + threadIdx.x;
    if (i < BBATCH * SSEQ) dst[i] = (float)tokens[i];
}

extern "C" void kernel_launch(void* const* d_in, const int* in_sizes, int n_in,
                              void* d_out, int out_size){
    const int*   tokens = (const int*)  d_in[0];
    const float* emb    = (const float*)d_in[1];
    const float* eWih0  = (const float*)d_in[2];
    const float* eWhh0  = (const float*)d_in[3];
    const float* ebih0  = (const float*)d_in[4];
    const float* ebhh0  = (const float*)d_in[5];
    const float* eWih1  = (const float*)d_in[6];
    const float* eWhh1  = (const float*)d_in[7];
    const float* ebih1  = (const float*)d_in[8];
    const float* ebhh1  = (const float*)d_in[9];
    const float* muW    = (const float*)d_in[10];
    const float* mub    = (const float*)d_in[11];
    const float* varW   = (const float*)d_in[12];
    const float* varb   = (const float*)d_in[13];
    const float* demb   = (const float*)d_in[14];
    const float* prjW   = (const float*)d_in[15];
    const float* prjb   = (const float*)d_in[16];
    const float* dWih0  = (const float*)d_in[17];
    const float* dWhh0  = (const float*)d_in[18];
    const float* dbih0  = (const float*)d_in[19];
    const float* dbhh0  = (const float*)d_in[20];
    const float* dWih1  = (const float*)d_in[21];
    const float* dWhh1  = (const float*)d_in[22];
    const float* dbih1  = (const float*)d_in[23];
    const float* dbhh1  = (const float*)d_in[24];
    const float* headW  = (const float*)d_in[25];
    const float* headb  = (const float*)d_in[26];
    float* out = (float*)d_out;
    int full = (out_size >= FULLN) ? 1 : 0;

    cudaFuncSetAttribute(enc_k, cudaFuncAttributeMaxDynamicSharedMemorySize, ENC_F * 4);
    cudaFuncSetAttribute(dec_k, cudaFuncAttributeMaxDynamicSharedMemorySize, DEC_F * 4);

    enc_k<<<128, NT, ENC_F * 4>>>(tokens, emb, eWih0, eWhh0, ebih0, ebhh0,
                                  eWih1, eWhh1, ebih1, ebhh1,
                                  muW, mub, varW, varb, prjW, prjb, out, full);
    dec_k<<<128, NT, DEC_F * 4>>>(demb, dWih0, dWhh0, dbih0, dbhh0,
                                  dWih1, dWhh1, dbih1, dbhh1, headW, headb, out);
    if (full)
        tok_cast_k<<<(BBATCH * SSEQ + 255) / 256, 256>>>(tokens, out + TOKOFF);
}

// round 14
// speedup vs baseline: 1.2264x; 1.2264x over previous
#include <cuda_runtime.h>
#include <cstdint>

typedef unsigned int u32;
typedef unsigned long long u64;

#define BBATCH 2048
#define SSEQ 256
#define NTOK 6
#define STARTTOK 4

#define RECONS_N (BBATCH*SSEQ*4)
#define TOKOFF RECONS_N
#define MUOFF (RECONS_N + BBATCH*SSEQ)
#define LVOFF (MUOFF + BBATCH*3)
#define FULLN (LVOFF + BBATCH*3)

// common SMEM float offsets
#define O_W1A 0        /* [d][u][4] = wir,whr,wiz,whz : 16384 */
#define O_W1B 16384    /* [d][u][2] = win,whn : 8192 */
#define O_W0A 24576    /* [d][u][4] = whr,whz,whn,pad : 16384 */
#define O_TAB 40960    /* 6*192 */
#define O_B0  42112
#define O_BI1 42304
#define O_BH1 42496
#define O_H0B 42688    /* [2][64][20] : 2560 */
#define O_H1B 45248    /* [2][64][20] : 2560 */
// encoder-only
#define O_MUW 47808
#define O_VARW 48000
#define O_MUB 48192
#define O_VARB 48196
#define O_PRJW 48200
#define O_PRJB 48392
#define O_ZS  48456
#define O_TOKS 48504   /* 4096 ints */
#define ENC_F 52600
// decoder-only
#define O_HW  47808    /* 256 */
#define O_HB2 48064    /* 4 */
#define O_K0  48068    /* 256 */
#define O_K1  48324    /* 256 */
#define O_TOKD 48580   /* 16 ints */
#define O_LSTG 48596   /* [4w*4v][16rows] = 256 */
#define DEC_F 48852

__device__ float g_hz[BBATCH*64];

// ---------- f32x2 helpers ----------
__device__ __forceinline__ void upk2(u64 v, float& a, float& b){
    asm("mov.b64 {%0,%1},%2;" : "=f"(a), "=f"(b) : "l"(v));
}
__device__ __forceinline__ u64 pack2(float x, float y){
    u64 r; asm("mov.b64 %0,{%1,%2};" : "=l"(r) : "f"(x), "f"(y)); return r;
}
__device__ __forceinline__ u64 dupf(float f){ return pack2(f, f); }
__device__ __forceinline__ u64 ff2(u64 a, u64 b, u64 c){
    u64 d; asm("fma.rn.f32x2 %0,%1,%2,%3;" : "=l"(d) : "l"(a), "l"(b), "l"(c)); return d;
}
__device__ __forceinline__ u64 add2(u64 a, u64 b){
    u64 c; asm("add.rn.f32x2 %0,%1,%2;" : "=l"(c) : "l"(a), "l"(b)); return c;
}
__device__ __forceinline__ u64 d2u(double d){ return (u64)__double_as_longlong(d); }

// ---------- threefry2x32-20 (exact JAX) ----------
__device__ __forceinline__ void threefry(u32 k0, u32 k1, u32 x0, u32 x1, u32& o0, u32& o1){
    u32 ks2 = k0 ^ k1 ^ 0x1BD11BDAu;
    x0 += k0; x1 += k1;
#define TFR(r) { x0 += x1; x1 = __funnelshift_l(x1, x1, (r)); x1 ^= x0; }
    TFR(13) TFR(15) TFR(26) TFR(6)   x0 += k1;  x1 += ks2 + 1u;
    TFR(17) TFR(29) TFR(16) TFR(24)  x0 += ks2; x1 += k0 + 2u;
    TFR(13) TFR(15) TFR(26) TFR(6)   x0 += k0;  x1 += k1 + 3u;
    TFR(17) TFR(29) TFR(16) TFR(24)  x0 += k1;  x1 += ks2 + 4u;
    TFR(13) TFR(15) TFR(26) TFR(6)   x0 += ks2; x1 += k0 + 5u;
#undef TFR
    o0 = x0; o1 = x1;
}
__device__ __forceinline__ u32 tf_bits32(u32 k0, u32 k1, u32 i){
    u32 a, b; threefry(k0, k1, 0u, i, a, b); return a ^ b;
}
__device__ __forceinline__ float bits2f(u32 b){
    return __uint_as_float((b >> 9) | 0x3f800000u) - 1.0f;
}
__device__ __forceinline__ float sigf(float x){ return 0.5f + 0.5f * tanhf(0.5f * x); }

__device__ __forceinline__ float erfinv_f(float x){
    float w = -log1pf(-x * x), p;
    if (w < 5.f){
        w -= 2.5f;
        p = 2.81022636e-08f;
        p = fmaf(p, w, 3.43273939e-07f);
        p = fmaf(p, w, -3.5233877e-06f);
        p = fmaf(p, w, -4.39150654e-06f);
        p = fmaf(p, w, 0.00021858087f);
        p = fmaf(p, w, -0.00125372503f);
        p = fmaf(p, w, -0.00417768164f);
        p = fmaf(p, w, 0.246640727f);
        p = fmaf(p, w, 1.50140941f);
    } else {
        w = sqrtf(w) - 3.f;
        p = -0.000200214257f;
        p = fmaf(p, w, 0.000100950558f);
        p = fmaf(p, w, 0.00134934322f);
        p = fmaf(p, w, -0.00367342844f);
        p = fmaf(p, w, 0.00573950773f);
        p = fmaf(p, w, -0.0076224613f);
        p = fmaf(p, w, 0.00943887047f);
        p = fmaf(p, w, 1.00167406f);
        p = fmaf(p, w, 2.83297682f);
    }
    return p * x;
}

// ---------- plain l0 matvec (decoder prologue only) ----------
__device__ __forceinline__ void l0mv(const float* h0c, const float* w0,
                                     u64* ar, u64* az, u64* an){
#pragma unroll
    for (int k = 0; k < 4; k++){ ar[k] = az[k] = an[k] = 0ull; }
#pragma unroll 4
    for (int d = 0; d < 64; d++){
        float4 w = *(const float4*)(w0 + d * 256);
        u64 WR = dupf(w.x), WZ = dupf(w.y), WN = dupf(w.z);
        double2 A = *(const double2*)(h0c + d * 20);
        double2 B = *(const double2*)(h0c + d * 20 + 4);
        u64 h[4] = { d2u(A.x), d2u(A.y), d2u(B.x), d2u(B.y) };
#pragma unroll
        for (int k = 0; k < 4; k++){
            ar[k] = ff2(h[k], WR, ar[k]);
            az[k] = ff2(h[k], WZ, az[k]);
            an[k] = ff2(h[k], WN, an[k]);
        }
    }
}

// ---------- FUSED matvec: l1mv(step s) + l0mv(step s+1) ----------
// xc = h0_new(s) (input to l1 AND input to next step's l0); hc = h1(s-1).
__device__ __forceinline__ void fused_mv(const float* xc, const float* hc,
                                         const float* w1a, const float* w1b,
                                         const float* w0,
                                         u64 pr[4], u64 pz[4], u64 pin[4], u64 phn[4],
                                         u64 ar[4], u64 az[4], u64 an[4]){
#pragma unroll
    for (int k = 0; k < 4; k++){
        pr[k]=pz[k]=pin[k]=phn[k]=0ull;
        ar[k]=az[k]=an[k]=0ull;
    }
#pragma unroll 4
    for (int d = 0; d < 64; d++){
        float4 wa = *(const float4*)(w1a + d * 256);
        float2 wb = *(const float2*)(w1b + d * 128);
        float4 w0v = *(const float4*)(w0 + d * 256);
        u64 WIR = dupf(wa.x), WHR = dupf(wa.y);
        u64 WIZ = dupf(wa.z), WHZ = dupf(wa.w);
        u64 WIN = dupf(wb.x), WHN = dupf(wb.y);
        u64 W0R = dupf(w0v.x), W0Z = dupf(w0v.y), W0N = dupf(w0v.z);
        double2 XA = *(const double2*)(xc + d * 20);
        double2 XB = *(const double2*)(xc + d * 20 + 4);
        double2 HA = *(const double2*)(hc + d * 20);
        double2 HB = *(const double2*)(hc + d * 20 + 4);
        u64 x[4] = { d2u(XA.x), d2u(XA.y), d2u(XB.x), d2u(XB.y) };
        u64 h[4] = { d2u(HA.x), d2u(HA.y), d2u(HB.x), d2u(HB.y) };
#pragma unroll
        for (int k = 0; k < 4; k++){
            pr[k]  = ff2(x[k], WIR, ff2(h[k], WHR, pr[k]));
            pz[k]  = ff2(x[k], WIZ, ff2(h[k], WHZ, pz[k]));
            pin[k] = ff2(x[k], WIN, pin[k]);
            phn[k] = ff2(h[k], WHN, phn[k]);
            ar[k]  = ff2(x[k], W0R, ar[k]);
            az[k]  = ff2(x[k], W0Z, az[k]);
            an[k]  = ff2(x[k], W0N, an[k]);
        }
    }
}

// L0 epilogue: tk[8] = tokens for rows 8rg..8rg+7; writes h0 pairs to h0n (+2k)
__device__ __forceinline__ void l0epi(const float* sm, float* h0n, int ug,
                                      const int* tk, const u64* ar, const u64* az,
                                      const u64* an, float b0r, float b0z, float b0n,
                                      float* hp0x, float* hp0y){
#pragma unroll
    for (int k = 0; k < 4; k++){
        const float* tb0 = sm + O_TAB + tk[2*k] * 192 + ug;
        const float* tb1 = sm + O_TAB + tk[2*k+1] * 192 + ug;
        float arx, ary, azx, azy, anx, any;
        upk2(ar[k], arx, ary); upk2(az[k], azx, azy); upk2(an[k], anx, any);
        float rx = sigf(tb0[0] + arx + b0r);
        float ry = sigf(tb1[0] + ary + b0r);
        float zx = sigf(tb0[64] + azx + b0z);
        float zy = sigf(tb1[64] + azy + b0z);
        float nx = tanhf(tb0[128] + rx * (anx + b0n));
        float ny = tanhf(tb1[128] + ry * (any + b0n));
        float hx = (1.f - zx) * nx + zx * hp0x[k];
        float hy = (1.f - zy) * ny + zy * hp0y[k];
        hp0x[k] = hx; hp0y[k] = hy;
        *(float2*)(h0n + 2 * k) = make_float2(hx, hy);
    }
}

__device__ __forceinline__ void l1epi(float* h1n, const u64* pr, const u64* pz,
                                      const u64* pin, const u64* phn,
                                      float bi1r, float bi1z, float bi1n,
                                      float bh1r, float bh1z, float bh1n,
                                      float* hp1x, float* hp1y){
#pragma unroll
    for (int k = 0; k < 4; k++){
        float prx, pry, pzx, pzy, pix, piy, phx, phy;
        upk2(pr[k], prx, pry); upk2(pz[k], pzx, pzy);
        upk2(pin[k], pix, piy); upk2(phn[k], phx, phy);
        float rx = sigf(prx + bi1r + bh1r);
        float ry = sigf(pry + bi1r + bh1r);
        float zx = sigf(pzx + bi1z + bh1z);
        float zy = sigf(pzy + bi1z + bh1z);
        float nx = tanhf(pix + bi1n + rx * (phx + bh1n));
        float ny = tanhf(piy + bi1n + ry * (phy + bh1n));
        float hx = (1.f - zx) * nx + zx * hp1x[k];
        float hy = (1.f - zy) * ny + zy * hp1y[k];
        hp1x[k] = hx; hp1y[k] = hy;
        *(float2*)(h1n + 2 * k) = make_float2(hx, hy);
    }
}

// ---------- weight staging ----------
__device__ __forceinline__ void stage_weights(float* sm, int tid,
    const float* Whh0, const float* Wih1, const float* Whh1,
    const float* bhh0, const float* bih1, const float* bhh1){
    for (int i = tid; i < 4096; i += 128){
        int u = i >> 6, d = i & 63;
        int o = (d * 64 + u);
        sm[O_W1A + o*4 + 0] = Wih1[u*64 + d];
        sm[O_W1A + o*4 + 1] = Whh1[u*64 + d];
        sm[O_W1A + o*4 + 2] = Wih1[(64+u)*64 + d];
        sm[O_W1A + o*4 + 3] = Whh1[(64+u)*64 + d];
        sm[O_W1B + o*2 + 0] = Wih1[(128+u)*64 + d];
        sm[O_W1B + o*2 + 1] = Whh1[(128+u)*64 + d];
        sm[O_W0A + o*4 + 0] = Whh0[u*64 + d];
        sm[O_W0A + o*4 + 1] = Whh0[(64+u)*64 + d];
        sm[O_W0A + o*4 + 2] = Whh0[(128+u)*64 + d];
        sm[O_W0A + o*4 + 3] = 0.f;
    }
    for (int i = tid; i < 192; i += 128){
        sm[O_B0 + i] = bhh0[i];
        sm[O_BI1 + i] = bih1[i];
        sm[O_BH1 + i] = bhh1[i];
    }
}

// =========================== ENCODER ===========================
__global__ void __launch_bounds__(128, 1) enc_k(
    const int* __restrict__ tokens, const float* __restrict__ emb,
    const float* __restrict__ Wih0, const float* __restrict__ Whh0,
    const float* __restrict__ bih0, const float* __restrict__ bhh0,
    const float* __restrict__ Wih1, const float* __restrict__ Whh1,
    const float* __restrict__ bih1, const float* __restrict__ bhh1,
    const float* __restrict__ muW, const float* __restrict__ mub,
    const float* __restrict__ varW, const float* __restrict__ varb,
    const float* __restrict__ prjW, const float* __restrict__ prjb,
    float* __restrict__ out, int wr_extra)
{
    extern __shared__ float sm[];
    int tid = threadIdx.x;
    stage_weights(sm, tid, Whh0, Wih1, Whh1, bhh0, bih1, bhh1);
    for (int i = tid; i < NTOK * 192; i += 128){
        int t = i / 192, u = i % 192;
        float s = bih0[u];
#pragma unroll
        for (int e = 0; e < 8; e++) s = fmaf(emb[t * 8 + e], Wih0[u * 8 + e], s);
        sm[O_TAB + i] = s;
    }
    for (int i = tid; i < 192; i += 128){
        sm[O_MUW + i] = muW[i]; sm[O_VARW + i] = varW[i]; sm[O_PRJW + i] = prjW[i];
    }
    if (tid < 3){ sm[O_MUB + tid] = mub[tid]; sm[O_VARB + tid] = varb[tid]; }
    for (int i = tid; i < 64; i += 128) sm[O_PRJB + i] = prjb[i];
    int base = blockIdx.x * 16;
    int* toksS = (int*)(sm + O_TOKS);
    for (int i = tid; i < 16 * 256; i += 128) toksS[i] = tokens[base * 256 + i];
    for (int i = tid; i < 1280; i += 128){ sm[O_H0B + i] = 0.f; sm[O_H1B + i] = 0.f; }
    __syncthreads();

    int warp = tid >> 5, lane = tid & 31;
    int ul = lane & 15, rg = lane >> 4;
    int ug = warp * 16 + ul;
    const float* w0  = sm + O_W0A + ug * 4;
    const float* w1a = sm + O_W1A + ug * 4;
    const float* w1b = sm + O_W1B + ug * 2;
    float b0r = sm[O_B0 + ug],  b0z = sm[O_B0 + 64 + ug],  b0n = sm[O_B0 + 128 + ug];
    float i1r = sm[O_BI1 + ug], i1z = sm[O_BI1 + 64 + ug], i1n = sm[O_BI1 + 128 + ug];
    float h1r = sm[O_BH1 + ug], h1z = sm[O_BH1 + 64 + ug], h1n = sm[O_BH1 + 128 + ug];

    float hp0x[4], hp0y[4], hp1x[4], hp1y[4];
#pragma unroll
    for (int k = 0; k < 4; k++){ hp0x[k] = hp0y[k] = hp1x[k] = hp1y[k] = 0.f; }

    // h0_init = 0 -> l0 matvec of step 0 is exactly 0
    u64 arC[4] = {0,0,0,0}, azC[4] = {0,0,0,0}, anC[4] = {0,0,0,0};

    for (int s = 0; s < 256; s++){
        int cb = s & 1, nb = cb ^ 1;
        int tk[8];
#pragma unroll
        for (int r = 0; r < 8; r++) tk[r] = toksS[(8 * rg + r) * 256 + s];
        l0epi(sm, sm + O_H0B + nb * 1280 + ug * 20 + 8 * rg, ug, tk,
              arC, azC, anC, b0r, b0z, b0n, hp0x, hp0y);
        __syncthreads();
        u64 pr[4], pz[4], pin[4], phn[4];
        fused_mv(sm + O_H0B + nb * 1280 + rg * 8, sm + O_H1B + cb * 1280 + rg * 8,
                 w1a, w1b, w0, pr, pz, pin, phn, arC, azC, anC);
        l1epi(sm + O_H1B + nb * 1280 + ug * 20 + 8 * rg, pr, pz, pin, phn,
              i1r, i1z, i1n, h1r, h1z, h1n, hp1x, hp1y);
    }
    __syncthreads();

    // final h1 in h1b buffer 0
    if (lane < 12){
        int r = lane / 3, j = lane % 3;
        int lr = warp * 4 + r;
        int row = base + lr;
        float m = sm[O_MUB + j], v = sm[O_VARB + j];
        for (int d = 0; d < 64; d++){
            float h = sm[O_H1B + d * 20 + lr];
            m = fmaf(h, sm[O_MUW + j * 64 + d], m);
            v = fmaf(h, sm[O_VARW + j * 64 + d], v);
        }
        u32 bits = tf_bits32(0u, 1u, (u32)(row * 3 + j));
        float f01 = bits2f(bits);
        const float LO = -0.99999994f;
        float u = fmaxf(LO, fmaf(f01, 2.0f, LO));
        float eps = 1.41421356f * erfinv_f(u);
        float z = fmaf(eps, expf(0.5f * v), m);
        sm[O_ZS + lr * 3 + j] = z;
        if (wr_extra){ out[MUOFF + row * 3 + j] = m; out[LVOFF + row * 3 + j] = v; }
    }
    __syncthreads();
    for (int i = tid; i < 1024; i += 128){
        int r = i >> 6, d = i & 63;
        float z0 = sm[O_ZS + r * 3];
        float z1 = sm[O_ZS + r * 3 + 1];
        float z2 = sm[O_ZS + r * 3 + 2];
        float hx = sm[O_PRJB + d] + z0 * sm[O_PRJW + d * 3] + z1 * sm[O_PRJW + d * 3 + 1]
                 + z2 * sm[O_PRJW + d * 3 + 2];
        g_hz[(base + r) * 64 + d] = hx;
    }
}

// =========================== DECODER ===========================
__global__ void __launch_bounds__(128, 1) dec_k(
    const float* __restrict__ dec_emb,
    const float* __restrict__ Wih0, const float* __restrict__ Whh0,
    const float* __restrict__ bih0, const float* __restrict__ bhh0,
    const float* __restrict__ Wih1, const float* __restrict__ Whh1,
    const float* __restrict__ bih1, const float* __restrict__ bhh1,
    const float* __restrict__ headW, const float* __restrict__ headb,
    float* __restrict__ out)
{
    extern __shared__ float sm[];
    int tid = threadIdx.x;
    stage_weights(sm, tid, Whh0, Wih1, Whh1, bhh0, bih1, bhh1);
    for (int i = tid; i < NTOK * 192; i += 128){
        int t = i / 192, u = i % 192;
        float s = bih0[u];
        for (int d = 0; d < 64; d++) s = fmaf(dec_emb[t * 64 + d], Wih0[u * 64 + d], s);
        sm[O_TAB + i] = s;
    }
    for (int i = tid; i < 256; i += 128) sm[O_HW + i] = headW[i];
    if (tid < 4) sm[O_HB2 + tid] = headb[tid];
    u32* K0 = (u32*)(sm + O_K0);
    u32* K1 = (u32*)(sm + O_K1);
    for (int i = tid; i < 256; i += 128){
        u32 a, b; threefry(0u, 2u, 0u, (u32)i, a, b);
        K0[i] = a; K1[i] = b;
    }
    int* tokD = (int*)(sm + O_TOKD);
    if (tid < 16) tokD[tid] = STARTTOK;
    int base = blockIdx.x * 16;
    for (int i = tid; i < 1024; i += 128){
        int r = i >> 6, d = i & 63;
        float v = g_hz[(base + r) * 64 + d];
        sm[O_H0B + d * 20 + r] = v;
        sm[O_H1B + d * 20 + r] = v;
    }
    __syncthreads();

    int warp = tid >> 5, lane = tid & 31;
    int ul = lane & 15, rg = lane >> 4;
    int ug = warp * 16 + ul;
    const float* w0  = sm + O_W0A + ug * 4;
    const float* w1a = sm + O_W1A + ug * 4;
    const float* w1b = sm + O_W1B + ug * 2;
    float b0r = sm[O_B0 + ug],  b0z = sm[O_B0 + 64 + ug],  b0n = sm[O_B0 + 128 + ug];
    float i1r = sm[O_BI1 + ug], i1z = sm[O_BI1 + 64 + ug], i1n = sm[O_BI1 + 128 + ug];
    float h1r = sm[O_BH1 + ug], h1z = sm[O_BH1 + 64 + ug], h1n = sm[O_BH1 + 128 + ug];
    u64 WV[4];
#pragma unroll
    for (int v = 0; v < 4; v++) WV[v] = dupf(sm[O_HW + v * 64 + ug]);

    float hp0x[4], hp0y[4], hp1x[4], hp1y[4];
#pragma unroll
    for (int k = 0; k < 4; k++){
        float2 h = *(const float2*)(sm + O_H0B + ug * 20 + 8 * rg + 2 * k);
        hp0x[k] = hp1x[k] = h.x;
        hp0y[k] = hp1y[k] = h.y;
    }

    // prologue: l0 matvec for step 0 on h0 = hz (buffer 0)
    u64 arC[4], azC[4], anC[4];
    l0mv(sm + O_H0B + rg * 8, w0, arC, azC, anC);

    const float TINYF = 1.17549435e-38f;
    for (int s = 0; s < 256; s++){
        int cb = s & 1, nb = cb ^ 1;
        int tk[8];
#pragma unroll
        for (int r = 0; r < 8; r++) tk[r] = tokD[8 * rg + r];
        l0epi(sm, sm + O_H0B + nb * 1280 + ug * 20 + 8 * rg, ug, tk,
              arC, azC, anC, b0r, b0z, b0n, hp0x, hp0y);
        __syncthreads();   // SYNC_B: new h0 visible
        u64 pr[4], pz[4], pin[4], phn[4];
        fused_mv(sm + O_H0B + nb * 1280 + rg * 8, sm + O_H1B + cb * 1280 + rg * 8,
                 w1a, w1b, w0, pr, pz, pin, phn, arC, azC, anC);
        l1epi(sm + O_H1B + nb * 1280 + ug * 20 + 8 * rg, pr, pz, pin, phn,
              i1r, i1z, i1n, h1r, h1z, h1n, hp1x, hp1y);

        // head partials per (pair, v), reduce over this warp's 16 units
        u64 pp[16];
#pragma unroll
        for (int k = 0; k < 4; k++){
            u64 hp = pack2(hp1x[k], hp1y[k]);
#pragma unroll
            for (int v = 0; v < 4; v++) pp[k * 4 + v] = ff2(hp, WV[v], 0ull);
        }
#pragma unroll
        for (int m = 1; m < 16; m <<= 1){
#pragma unroll
            for (int j = 0; j < 16; j++){
                double o = __shfl_xor_sync(0xffffffffu, __longlong_as_double((long long)pp[j]), m);
                pp[j] = add2(pp[j], d2u(o));
            }
        }
        if (ul == 0){
#pragma unroll
            for (int k = 0; k < 4; k++)
#pragma unroll
                for (int v = 0; v < 4; v++){
                    float a, b; upk2(pp[k * 4 + v], a, b);
                    *(float2*)(sm + O_LSTG + (warp * 4 + v) * 16 + 8 * rg + 2 * k)
                        = make_float2(a, b);
                }
        }
        __syncthreads();   // SYNC_C: LSTG + h1 + token ordering for next step

        // sample: warp handles its 4 rows
        {
            int k = lane & 15, r = k >> 2, v = k & 3;
            int lr = warp * 4 + r;
            int row = base + lr;
            float sum = ((sm[O_LSTG + v * 16 + lr] + sm[O_LSTG + (4 + v) * 16 + lr])
                         + sm[O_LSTG + (8 + v) * 16 + lr]) + sm[O_LSTG + (12 + v) * 16 + lr];
            float logit = sum + sm[O_HB2 + v];
            u32 bits = tf_bits32(K0[s], K1[s], (u32)(row * 4 + v));
            float f01 = bits2f(bits);
            float u = fmaxf(TINYF, f01 + TINYF);
            float g = -logf(-logf(u));
            float y = logit + g;
            float mx = logit;
            mx = fmaxf(mx, __shfl_xor_sync(0xffffffffu, mx, 1));
            mx = fmaxf(mx, __shfl_xor_sync(0xffffffffu, mx, 2));
            float e = expf(logit - mx);
            float den = e;
            den += __shfl_xor_sync(0xffffffffu, den, 1);
            den += __shfl_xor_sync(0xffffffffu, den, 2);
            if (lane < 16) out[((size_t)row * 256 + s) * 4 + v] = e / den;
            float by = y; int bi = v;
            { float oy = __shfl_xor_sync(0xffffffffu, by, 1);
              int   oi = __shfl_xor_sync(0xffffffffu, bi, 1);
              if (oy > by || (oy == by && oi < bi)){ by = oy; bi = oi; } }
            { float oy = __shfl_xor_sync(0xffffffffu, by, 2);
              int   oi = __shfl_xor_sync(0xffffffffu, bi, 2);
              if (oy > by || (oy == by && oi < bi)){ by = oy; bi = oi; } }
            if (lane < 16 && v == 0) tokD[lr] = bi;
        }
        __syncthreads();   // SYNC_A for next step: tokD writes visible before l0epi(s+1)
    }
}

__global__ void tok_cast_k(const int* __restrict__ tokens, float* __restrict__ dst){
    int i = blockIdx.x * blockDim.x + threadIdx.x;
    if (i < BBATCH * SSEQ) dst[i] = (float)tokens[i];
}

extern "C" void kernel_launch(void* const* d_in, const int* in_sizes, int n_in,
                              void* d_out, int out_size){
    const int*   tokens = (const int*)  d_in[0];
    const float* emb    = (const float*)d_in[1];
    const float* eWih0  = (const float*)d_in[2];
    const float* eWhh0  = (const float*)d_in[3];
    const float* ebih0  = (const float*)d_in[4];
    const float* ebhh0  = (const float*)d_in[5];
    const float* eWih1  = (const float*)d_in[6];
    const float* eWhh1  = (const float*)d_in[7];
    const float* ebih1  = (const float*)d_in[8];
    const float* ebhh1  = (const float*)d_in[9];
    const float* muW    = (const float*)d_in[10];
    const float* mub    = (const float*)d_in[11];
    const float* varW   = (const float*)d_in[12];
    const float* varb   = (const float*)d_in[13];
    const float* demb   = (const float*)d_in[14];
    const float* prjW   = (const float*)d_in[15];
    const float* prjb   = (const float*)d_in[16];
    const float* dWih0  = (const float*)d_in[17];
    const float* dWhh0  = (const float*)d_in[18];
    const float* dbih0  = (const float*)d_in[19];
    const float* dbhh0  = (const float*)d_in[20];
    const float* dWih1  = (const float*)d_in[21];
    const float* dWhh1  = (const float*)d_in[22];
    const float* dbih1  = (const float*)d_in[23];
    const float* dbhh1  = (const float*)d_in[24];
    const float* headW  = (const float*)d_in[25];
    const float* headb  = (const float*)d_in[26];
    float* out = (float*)d_out;
    int full = (out_size >= FULLN) ? 1 : 0;

    cudaFuncSetAttribute(enc_k, cudaFuncAttributeMaxDynamicSharedMemorySize, ENC_F * 4);
    cudaFuncSetAttribute(dec_k, cudaFuncAttributeMaxDynamicSharedMemorySize, DEC_F * 4);

    enc_k<<<128, 128, ENC_F * 4>>>(tokens, emb, eWih0, eWhh0, ebih0, ebhh0,
                                   eWih1, eWhh1, ebih1, ebhh1,
                                   muW, mub, varW, varb, prjW, prjb, out, full);
    dec_k<<<128, 128, DEC_F * 4>>>(demb, dWih0, dWhh0, dbih0, dbhh0,
                                   dWih1, dWhh1, dbih1, dbhh1, headW, headb, out);
    if (full)
        tok_cast_k<<<(BBATCH * SSEQ + 255) / 256, 256>>>(tokens, out + TOKOFF);
}

// round 15
// speedup vs baseline: 1.2268x; 1.0003x over previous
#include <cuda_runtime.h>
#include <cstdint>

typedef unsigned int u32;
typedef unsigned long long u64;

#define BBATCH 2048
#define SSEQ 256
#define NTOK 6
#define STARTTOK 4

#define RECONS_N (BBATCH*SSEQ*4)
#define TOKOFF RECONS_N
#define MUOFF (RECONS_N + BBATCH*SSEQ)
#define LVOFF (MUOFF + BBATCH*3)
#define FULLN (LVOFF + BBATCH*3)

// common SMEM float offsets
#define O_W1A 0        /* [d][u][4] = wir,whr,wiz,whz : 16384 */
#define O_W1B 16384    /* [d][u][2] = win,whn : 8192 */
#define O_W0A 24576    /* [d][u][4] = whr,whz,whn,pad : 16384 */
#define O_TAB 40960    /* 6*192 */
#define O_B0  42112
#define O_BI1 42304
#define O_BH1 42496
#define O_H0B 42688    /* [2][64][20] : 2560 */
#define O_H1B 45248    /* [2][64][20] : 2560 */
// encoder-only
#define O_MUW 47808
#define O_VARW 48000
#define O_MUB 48192
#define O_VARB 48196
#define O_PRJW 48200
#define O_PRJB 48392
#define O_ZS  48456
#define O_TOKS 48504   /* 4096 ints */
#define ENC_F 52600
// decoder-only
#define O_HW  47808    /* 256 */
#define O_HB2 48064    /* 4 */
#define O_K0  48068    /* 256 */
#define O_K1  48324    /* 256 */
#define O_TOKD 48580   /* 16 ints */
#define O_LSTG 48596   /* [4w*4v][16rows] = 256 */
#define DEC_F 48852

__device__ float g_hz[BBATCH*64];

// ---------- f32x2 helpers ----------
__device__ __forceinline__ void upk2(u64 v, float& a, float& b){
    asm("mov.b64 {%0,%1},%2;" : "=f"(a), "=f"(b) : "l"(v));
}
__device__ __forceinline__ u64 pack2(float x, float y){
    u64 r; asm("mov.b64 %0,{%1,%2};" : "=l"(r) : "f"(x), "f"(y)); return r;
}
__device__ __forceinline__ u64 dupf(float f){ return pack2(f, f); }
__device__ __forceinline__ u64 ff2(u64 a, u64 b, u64 c){
    u64 d; asm("fma.rn.f32x2 %0,%1,%2,%3;" : "=l"(d) : "l"(a), "l"(b), "l"(c)); return d;
}
__device__ __forceinline__ u64 add2(u64 a, u64 b){
    u64 c; asm("add.rn.f32x2 %0,%1,%2;" : "=l"(c) : "l"(a), "l"(b)); return c;
}
__device__ __forceinline__ u64 d2u(double d){ return (u64)__double_as_longlong(d); }

// ---------- threefry2x32-20 (exact JAX) ----------
__device__ __forceinline__ void threefry(u32 k0, u32 k1, u32 x0, u32 x1, u32& o0, u32& o1){
    u32 ks2 = k0 ^ k1 ^ 0x1BD11BDAu;
    x0 += k0; x1 += k1;
#define TFR(r) { x0 += x1; x1 = __funnelshift_l(x1, x1, (r)); x1 ^= x0; }
    TFR(13) TFR(15) TFR(26) TFR(6)   x0 += k1;  x1 += ks2 + 1u;
    TFR(17) TFR(29) TFR(16) TFR(24)  x0 += ks2; x1 += k0 + 2u;
    TFR(13) TFR(15) TFR(26) TFR(6)   x0 += k0;  x1 += k1 + 3u;
    TFR(17) TFR(29) TFR(16) TFR(24)  x0 += k1;  x1 += ks2 + 4u;
    TFR(13) TFR(15) TFR(26) TFR(6)   x0 += ks2; x1 += k0 + 5u;
#undef TFR
    o0 = x0; o1 = x1;
}
__device__ __forceinline__ u32 tf_bits32(u32 k0, u32 k1, u32 i){
    u32 a, b; threefry(k0, k1, 0u, i, a, b); return a ^ b;
}
__device__ __forceinline__ float bits2f(u32 b){
    return __uint_as_float((b >> 9) | 0x3f800000u) - 1.0f;
}
__device__ __forceinline__ float sigf(float x){ return 0.5f + 0.5f * tanhf(0.5f * x); }

__device__ __forceinline__ float erfinv_f(float x){
    float w = -log1pf(-x * x), p;
    if (w < 5.f){
        w -= 2.5f;
        p = 2.81022636e-08f;
        p = fmaf(p, w, 3.43273939e-07f);
        p = fmaf(p, w, -3.5233877e-06f);
        p = fmaf(p, w, -4.39150654e-06f);
        p = fmaf(p, w, 0.00021858087f);
        p = fmaf(p, w, -0.00125372503f);
        p = fmaf(p, w, -0.00417768164f);
        p = fmaf(p, w, 0.246640727f);
        p = fmaf(p, w, 1.50140941f);
    } else {
        w = sqrtf(w) - 3.f;
        p = -0.000200214257f;
        p = fmaf(p, w, 0.000100950558f);
        p = fmaf(p, w, 0.00134934322f);
        p = fmaf(p, w, -0.00367342844f);
        p = fmaf(p, w, 0.00573950773f);
        p = fmaf(p, w, -0.0076224613f);
        p = fmaf(p, w, 0.00943887047f);
        p = fmaf(p, w, 1.00167406f);
        p = fmaf(p, w, 2.83297682f);
    }
    return p * x;
}

// ---------- plain l0 matvec (decoder prologue only) ----------
__device__ __forceinline__ void l0mv(const float* h0c, const float* w0,
                                     u64* ar, u64* az, u64* an){
#pragma unroll
    for (int k = 0; k < 4; k++){ ar[k] = az[k] = an[k] = 0ull; }
#pragma unroll 4
    for (int d = 0; d < 64; d++){
        float4 w = *(const float4*)(w0 + d * 256);
        u64 WR = dupf(w.x), WZ = dupf(w.y), WN = dupf(w.z);
        double2 A = *(const double2*)(h0c + d * 20);
        double2 B = *(const double2*)(h0c + d * 20 + 4);
        u64 h[4] = { d2u(A.x), d2u(A.y), d2u(B.x), d2u(B.y) };
#pragma unroll
        for (int k = 0; k < 4; k++){
            ar[k] = ff2(h[k], WR, ar[k]);
            az[k] = ff2(h[k], WZ, az[k]);
            an[k] = ff2(h[k], WN, an[k]);
        }
    }
}

// ---------- FUSED matvec: l1mv(step s) + l0mv(step s+1) ----------
// xc = h0_new(s) (input to l1 AND input to next step's l0); hc = h1(s-1).
__device__ __forceinline__ void fused_mv(const float* xc, const float* hc,
                                         const float* w1a, const float* w1b,
                                         const float* w0,
                                         u64 pr[4], u64 pz[4], u64 pin[4], u64 phn[4],
                                         u64 ar[4], u64 az[4], u64 an[4]){
#pragma unroll
    for (int k = 0; k < 4; k++){
        pr[k]=pz[k]=pin[k]=phn[k]=0ull;
        ar[k]=az[k]=an[k]=0ull;
    }
#pragma unroll 4
    for (int d = 0; d < 64; d++){
        float4 wa = *(const float4*)(w1a + d * 256);
        float2 wb = *(const float2*)(w1b + d * 128);
        float4 w0v = *(const float4*)(w0 + d * 256);
        u64 WIR = dupf(wa.x), WHR = dupf(wa.y);
        u64 WIZ = dupf(wa.z), WHZ = dupf(wa.w);
        u64 WIN = dupf(wb.x), WHN = dupf(wb.y);
        u64 W0R = dupf(w0v.x), W0Z = dupf(w0v.y), W0N = dupf(w0v.z);
        double2 XA = *(const double2*)(xc + d * 20);
        double2 XB = *(const double2*)(xc + d * 20 + 4);
        double2 HA = *(const double2*)(hc + d * 20);
        double2 HB = *(const double2*)(hc + d * 20 + 4);
        u64 x[4] = { d2u(XA.x), d2u(XA.y), d2u(XB.x), d2u(XB.y) };
        u64 h[4] = { d2u(HA.x), d2u(HA.y), d2u(HB.x), d2u(HB.y) };
#pragma unroll
        for (int k = 0; k < 4; k++){
            pr[k]  = ff2(x[k], WIR, ff2(h[k], WHR, pr[k]));
            pz[k]  = ff2(x[k], WIZ, ff2(h[k], WHZ, pz[k]));
            pin[k] = ff2(x[k], WIN, pin[k]);
            phn[k] = ff2(h[k], WHN, phn[k]);
            ar[k]  = ff2(x[k], W0R, ar[k]);
            az[k]  = ff2(x[k], W0Z, az[k]);
            an[k]  = ff2(x[k], W0N, an[k]);
        }
    }
}

// L0 epilogue: tk[8] = tokens for rows 8rg..8rg+7; writes h0 pairs to h0n (+2k)
__device__ __forceinline__ void l0epi(const float* sm, float* h0n, int ug,
                                      const int* tk, const u64* ar, const u64* az,
                                      const u64* an, float b0r, float b0z, float b0n,
                                      float* hp0x, float* hp0y){
#pragma unroll
    for (int k = 0; k < 4; k++){
        const float* tb0 = sm + O_TAB + tk[2*k] * 192 + ug;
        const float* tb1 = sm + O_TAB + tk[2*k+1] * 192 + ug;
        float arx, ary, azx, azy, anx, any;
        upk2(ar[k], arx, ary); upk2(az[k], azx, azy); upk2(an[k], anx, any);
        float rx = sigf(tb0[0] + arx + b0r);
        float ry = sigf(tb1[0] + ary + b0r);
        float zx = sigf(tb0[64] + azx + b0z);
        float zy = sigf(tb1[64] + azy + b0z);
        float nx = tanhf(tb0[128] + rx * (anx + b0n));
        float ny = tanhf(tb1[128] + ry * (any + b0n));
        float hx = (1.f - zx) * nx + zx * hp0x[k];
        float hy = (1.f - zy) * ny + zy * hp0y[k];
        hp0x[k] = hx; hp0y[k] = hy;
        *(float2*)(h0n + 2 * k) = make_float2(hx, hy);
    }
}

__device__ __forceinline__ void l1epi(float* h1n, const u64* pr, const u64* pz,
                                      const u64* pin, const u64* phn,
                                      float bi1r, float bi1z, float bi1n,
                                      float bh1r, float bh1z, float bh1n,
                                      float* hp1x, float* hp1y){
#pragma unroll
    for (int k = 0; k < 4; k++){
        float prx, pry, pzx, pzy, pix, piy, phx, phy;
        upk2(pr[k], prx, pry); upk2(pz[k], pzx, pzy);
        upk2(pin[k], pix, piy); upk2(phn[k], phx, phy);
        float rx = sigf(prx + bi1r + bh1r);
        float ry = sigf(pry + bi1r + bh1r);
        float zx = sigf(pzx + bi1z + bh1z);
        float zy = sigf(pzy + bi1z + bh1z);
        float nx = tanhf(pix + bi1n + rx * (phx + bh1n));
        float ny = tanhf(piy + bi1n + ry * (phy + bh1n));
        float hx = (1.f - zx) * nx + zx * hp1x[k];
        float hy = (1.f - zy) * ny + zy * hp1y[k];
        hp1x[k] = hx; hp1y[k] = hy;
        *(float2*)(h1n + 2 * k) = make_float2(hx, hy);
    }
}

// ---------- weight staging ----------
__device__ __forceinline__ void stage_weights(float* sm, int tid,
    const float* Whh0, const float* Wih1, const float* Whh1,
    const float* bhh0, const float* bih1, const float* bhh1){
    for (int i = tid; i < 4096; i += 128){
        int u = i >> 6, d = i & 63;
        int o = (d * 64 + u);
        sm[O_W1A + o*4 + 0] = Wih1[u*64 + d];
        sm[O_W1A + o*4 + 1] = Whh1[u*64 + d];
        sm[O_W1A + o*4 + 2] = Wih1[(64+u)*64 + d];
        sm[O_W1A + o*4 + 3] = Whh1[(64+u)*64 + d];
        sm[O_W1B + o*2 + 0] = Wih1[(128+u)*64 + d];
        sm[O_W1B + o*2 + 1] = Whh1[(128+u)*64 + d];
        sm[O_W0A + o*4 + 0] = Whh0[u*64 + d];
        sm[O_W0A + o*4 + 1] = Whh0[(64+u)*64 + d];
        sm[O_W0A + o*4 + 2] = Whh0[(128+u)*64 + d];
        sm[O_W0A + o*4 + 3] = 0.f;
    }
    for (int i = tid; i < 192; i += 128){
        sm[O_B0 + i] = bhh0[i];
        sm[O_BI1 + i] = bih1[i];
        sm[O_BH1 + i] = bhh1[i];
    }
}

// =========================== ENCODER ===========================
__global__ void __launch_bounds__(128, 1) enc_k(
    const int* __restrict__ tokens, const float* __restrict__ emb,
    const float* __restrict__ Wih0, const float* __restrict__ Whh0,
    const float* __restrict__ bih0, const float* __restrict__ bhh0,
    const float* __restrict__ Wih1, const float* __restrict__ Whh1,
    const float* __restrict__ bih1, const float* __restrict__ bhh1,
    const float* __restrict__ muW, const float* __restrict__ mub,
    const float* __restrict__ varW, const float* __restrict__ varb,
    const float* __restrict__ prjW, const float* __restrict__ prjb,
    float* __restrict__ out, int wr_extra)
{
    extern __shared__ float sm[];
    int tid = threadIdx.x;
    stage_weights(sm, tid, Whh0, Wih1, Whh1, bhh0, bih1, bhh1);
    for (int i = tid; i < NTOK * 192; i += 128){
        int t = i / 192, u = i % 192;
        float s = bih0[u];
#pragma unroll
        for (int e = 0; e < 8; e++) s = fmaf(emb[t * 8 + e], Wih0[u * 8 + e], s);
        sm[O_TAB + i] = s;
    }
    for (int i = tid; i < 192; i += 128){
        sm[O_MUW + i] = muW[i]; sm[O_VARW + i] = varW[i]; sm[O_PRJW + i] = prjW[i];
    }
    if (tid < 3){ sm[O_MUB + tid] = mub[tid]; sm[O_VARB + tid] = varb[tid]; }
    for (int i = tid; i < 64; i += 128) sm[O_PRJB + i] = prjb[i];
    int base = blockIdx.x * 16;
    int* toksS = (int*)(sm + O_TOKS);
    for (int i = tid; i < 16 * 256; i += 128) toksS[i] = tokens[base * 256 + i];
    for (int i = tid; i < 1280; i += 128){ sm[O_H0B + i] = 0.f; sm[O_H1B + i] = 0.f; }
    __syncthreads();

    int warp = tid >> 5, lane = tid & 31;
    int ul = lane & 15, rg = lane >> 4;
    int ug = warp * 16 + ul;
    const float* w0  = sm + O_W0A + ug * 4;
    const float* w1a = sm + O_W1A + ug * 4;
    const float* w1b = sm + O_W1B + ug * 2;
    float b0r = sm[O_B0 + ug],  b0z = sm[O_B0 + 64 + ug],  b0n = sm[O_B0 + 128 + ug];
    float i1r = sm[O_BI1 + ug], i1z = sm[O_BI1 + 64 + ug], i1n = sm[O_BI1 + 128 + ug];
    float h1r = sm[O_BH1 + ug], h1z = sm[O_BH1 + 64 + ug], h1n = sm[O_BH1 + 128 + ug];

    float hp0x[4], hp0y[4], hp1x[4], hp1y[4];
#pragma unroll
    for (int k = 0; k < 4; k++){ hp0x[k] = hp0y[k] = hp1x[k] = hp1y[k] = 0.f; }

    // h0_init = 0 -> l0 matvec of step 0 is exactly 0
    u64 arC[4] = {0,0,0,0}, azC[4] = {0,0,0,0}, anC[4] = {0,0,0,0};

    for (int s = 0; s < 256; s++){
        int cb = s & 1, nb = cb ^ 1;
        int tk[8];
#pragma unroll
        for (int r = 0; r < 8; r++) tk[r] = toksS[(8 * rg + r) * 256 + s];
        l0epi(sm, sm + O_H0B + nb * 1280 + ug * 20 + 8 * rg, ug, tk,
              arC, azC, anC, b0r, b0z, b0n, hp0x, hp0y);
        __syncthreads();
        u64 pr[4], pz[4], pin[4], phn[4];
        fused_mv(sm + O_H0B + nb * 1280 + rg * 8, sm + O_H1B + cb * 1280 + rg * 8,
                 w1a, w1b, w0, pr, pz, pin, phn, arC, azC, anC);
        l1epi(sm + O_H1B + nb * 1280 + ug * 20 + 8 * rg, pr, pz, pin, phn,
              i1r, i1z, i1n, h1r, h1z, h1n, hp1x, hp1y);
    }
    __syncthreads();

    // final h1 in h1b buffer 0
    if (lane < 12){
        int r = lane / 3, j = lane % 3;
        int lr = warp * 4 + r;
        int row = base + lr;
        float m = sm[O_MUB + j], v = sm[O_VARB + j];
        for (int d = 0; d < 64; d++){
            float h = sm[O_H1B + d * 20 + lr];
            m = fmaf(h, sm[O_MUW + j * 64 + d], m);
            v = fmaf(h, sm[O_VARW + j * 64 + d], v);
        }
        u32 bits = tf_bits32(0u, 1u, (u32)(row * 3 + j));
        float f01 = bits2f(bits);
        const float LO = -0.99999994f;
        float u = fmaxf(LO, fmaf(f01, 2.0f, LO));
        float eps = 1.41421356f * erfinv_f(u);
        float z = fmaf(eps, expf(0.5f * v), m);
        sm[O_ZS + lr * 3 + j] = z;
        if (wr_extra){ out[MUOFF + row * 3 + j] = m; out[LVOFF + row * 3 + j] = v; }
    }
    __syncthreads();
    for (int i = tid; i < 1024; i += 128){
        int r = i >> 6, d = i & 63;
        float z0 = sm[O_ZS + r * 3];
        float z1 = sm[O_ZS + r * 3 + 1];
        float z2 = sm[O_ZS + r * 3 + 2];
        float hx = sm[O_PRJB + d] + z0 * sm[O_PRJW + d * 3] + z1 * sm[O_PRJW + d * 3 + 1]
                 + z2 * sm[O_PRJW + d * 3 + 2];
        g_hz[(base + r) * 64 + d] = hx;
    }
}

// =========================== DECODER ===========================
__global__ void __launch_bounds__(128, 1) dec_k(
    const float* __restrict__ dec_emb,
    const float* __restrict__ Wih0, const float* __restrict__ Whh0,
    const float* __restrict__ bih0, const float* __restrict__ bhh0,
    const float* __restrict__ Wih1, const float* __restrict__ Whh1,
    const float* __restrict__ bih1, const float* __restrict__ bhh1,
    const float* __restrict__ headW, const float* __restrict__ headb,
    float* __restrict__ out)
{
    extern __shared__ float sm[];
    int tid = threadIdx.x;
    stage_weights(sm, tid, Whh0, Wih1, Whh1, bhh0, bih1, bhh1);
    for (int i = tid; i < NTOK * 192; i += 128){
        int t = i / 192, u = i % 192;
        float s = bih0[u];
        for (int d = 0; d < 64; d++) s = fmaf(dec_emb[t * 64 + d], Wih0[u * 64 + d], s);
        sm[O_TAB + i] = s;
    }
    for (int i = tid; i < 256; i += 128) sm[O_HW + i] = headW[i];
    if (tid < 4) sm[O_HB2 + tid] = headb[tid];
    u32* K0 = (u32*)(sm + O_K0);
    u32* K1 = (u32*)(sm + O_K1);
    for (int i = tid; i < 256; i += 128){
        u32 a, b; threefry(0u, 2u, 0u, (u32)i, a, b);
        K0[i] = a; K1[i] = b;
    }
    int* tokD = (int*)(sm + O_TOKD);
    if (tid < 16) tokD[tid] = STARTTOK;
    int base = blockIdx.x * 16;
    for (int i = tid; i < 1024; i += 128){
        int r = i >> 6, d = i & 63;
        float v = g_hz[(base + r) * 64 + d];
        sm[O_H0B + d * 20 + r] = v;
        sm[O_H1B + d * 20 + r] = v;
    }
    __syncthreads();

    int warp = tid >> 5, lane = tid & 31;
    int ul = lane & 15, rg = lane >> 4;
    int ug = warp * 16 + ul;
    const float* w0  = sm + O_W0A + ug * 4;
    const float* w1a = sm + O_W1A + ug * 4;
    const float* w1b = sm + O_W1B + ug * 2;
    float b0r = sm[O_B0 + ug],  b0z = sm[O_B0 + 64 + ug],  b0n = sm[O_B0 + 128 + ug];
    float i1r = sm[O_BI1 + ug], i1z = sm[O_BI1 + 64 + ug], i1n = sm[O_BI1 + 128 + ug];
    float h1r = sm[O_BH1 + ug], h1z = sm[O_BH1 + 64 + ug], h1n = sm[O_BH1 + 128 + ug];
    u64 WV[4];
#pragma unroll
    for (int v = 0; v < 4; v++) WV[v] = dupf(sm[O_HW + v * 64 + ug]);

    float hp0x[4], hp0y[4], hp1x[4], hp1y[4];
#pragma unroll
    for (int k = 0; k < 4; k++){
        float2 h = *(const float2*)(sm + O_H0B + ug * 20 + 8 * rg + 2 * k);
        hp0x[k] = hp1x[k] = h.x;
        hp0y[k] = hp1y[k] = h.y;
    }

    // prologue: l0 matvec for step 0 on h0 = hz (buffer 0)
    u64 arC[4], azC[4], anC[4];
    l0mv(sm + O_H0B + rg * 8, w0, arC, azC, anC);

    const float TINYF = 1.17549435e-38f;
    for (int s = 0; s < 256; s++){
        int cb = s & 1, nb = cb ^ 1;
        int tk[8];
#pragma unroll
        for (int r = 0; r < 8; r++) tk[r] = tokD[8 * rg + r];
        l0epi(sm, sm + O_H0B + nb * 1280 + ug * 20 + 8 * rg, ug, tk,
              arC, azC, anC, b0r, b0z, b0n, hp0x, hp0y);
        __syncthreads();   // SYNC_B: new h0 visible
        u64 pr[4], pz[4], pin[4], phn[4];
        fused_mv(sm + O_H0B + nb * 1280 + rg * 8, sm + O_H1B + cb * 1280 + rg * 8,
                 w1a, w1b, w0, pr, pz, pin, phn, arC, azC, anC);
        l1epi(sm + O_H1B + nb * 1280 + ug * 20 + 8 * rg, pr, pz, pin, phn,
              i1r, i1z, i1n, h1r, h1z, h1n, hp1x, hp1y);

        // head partials per (pair, v), reduce over this warp's 16 units
        u64 pp[16];
#pragma unroll
        for (int k = 0; k < 4; k++){
            u64 hp = pack2(hp1x[k], hp1y[k]);
#pragma unroll
            for (int v = 0; v < 4; v++) pp[k * 4 + v] = ff2(hp, WV[v], 0ull);
        }
#pragma unroll
        for (int m = 1; m < 16; m <<= 1){
#pragma unroll
            for (int j = 0; j < 16; j++){
                double o = __shfl_xor_sync(0xffffffffu, __longlong_as_double((long long)pp[j]), m);
                pp[j] = add2(pp[j], d2u(o));
            }
        }
        if (ul == 0){
#pragma unroll
            for (int k = 0; k < 4; k++)
#pragma unroll
                for (int v = 0; v < 4; v++){
                    float a, b; upk2(pp[k * 4 + v], a, b);
                    *(float2*)(sm + O_LSTG + (warp * 4 + v) * 16 + 8 * rg + 2 * k)
                        = make_float2(a, b);
                }
        }
        __syncthreads();   // SYNC_C: LSTG + h1 + token ordering for next step

        // sample: warp handles its 4 rows
        {
            int k = lane & 15, r = k >> 2, v = k & 3;
            int lr = warp * 4 + r;
            int row = base + lr;
            float sum = ((sm[O_LSTG + v * 16 + lr] + sm[O_LSTG + (4 + v) * 16 + lr])
                         + sm[O_LSTG + (8 + v) * 16 + lr]) + sm[O_LSTG + (12 + v) * 16 + lr];
            float logit = sum + sm[O_HB2 + v];
            u32 bits = tf_bits32(K0[s], K1[s], (u32)(row * 4 + v));
            float f01 = bits2f(bits);
            float u = fmaxf(TINYF, f01 + TINYF);
            float g = -logf(-logf(u));
            float y = logit + g;
            float mx = logit;
            mx = fmaxf(mx, __shfl_xor_sync(0xffffffffu, mx, 1));
            mx = fmaxf(mx, __shfl_xor_sync(0xffffffffu, mx, 2));
            float e = expf(logit - mx);
            float den = e;
            den += __shfl_xor_sync(0xffffffffu, den, 1);
            den += __shfl_xor_sync(0xffffffffu, den, 2);
            if (lane < 16) out[((size_t)row * 256 + s) * 4 + v] = e / den;
            float by = y; int bi = v;
            { float oy = __shfl_xor_sync(0xffffffffu, by, 1);
              int   oi = __shfl_xor_sync(0xffffffffu, bi, 1);
              if (oy > by || (oy == by && oi < bi)){ by = oy; bi = oi; } }
            { float oy = __shfl_xor_sync(0xffffffffu, by, 2);
              int   oi = __shfl_xor_sync(0xffffffffu, bi, 2);
              if (oy > by || (oy == by && oi < bi)){ by = oy; bi = oi; } }
            if (lane < 16 && v == 0) tokD[lr] = bi;
        }
        __syncthreads();   // SYNC_A for next step: tokD writes visible before l0epi(s+1)
    }
}

__global__ void tok_cast_k(const int* __restrict__ tokens, float* __restrict__ dst){
    int i = blockIdx.x * blockDim.x + threadIdx.x;
    if (i < BBATCH * SSEQ) dst[i] = (float)tokens[i];
}

extern "C" void kernel_launch(void* const* d_in, const int* in_sizes, int n_in,
                              void* d_out, int out_size){
    const int*   tokens = (const int*)  d_in[0];
    const float* emb    = (const float*)d_in[1];
    const float* eWih0  = (const float*)d_in[2];
    const float* eWhh0  = (const float*)d_in[3];
    const float* ebih0  = (const float*)d_in[4];
    const float* ebhh0  = (const float*)d_in[5];
    const float* eWih1  = (const float*)d_in[6];
    const float* eWhh1  = (const float*)d_in[7];
    const float* ebih1  = (const float*)d_in[8];
    const float* ebhh1  = (const float*)d_in[9];
    const float* muW    = (const float*)d_in[10];
    const float* mub    = (const float*)d_in[11];
    const float* varW   = (const float*)d_in[12];
    const float* varb   = (const float*)d_in[13];
    const float* demb   = (const float*)d_in[14];
    const float* prjW   = (const float*)d_in[15];
    const float* prjb   = (const float*)d_in[16];
    const float* dWih0  = (const float*)d_in[17];
    const float* dWhh0  = (const float*)d_in[18];
    const float* dbih0  = (const float*)d_in[19];
    const float* dbhh0  = (const float*)d_in[20];
    const float* dWih1  = (const float*)d_in[21];
    const float* dWhh1  = (const float*)d_in[22];
    const float* dbih1  = (const float*)d_in[23];
    const float* dbhh1  = (const float*)d_in[24];
    const float* headW  = (const float*)d_in[25];
    const float* headb  = (const float*)d_in[26];
    float* out = (float*)d_out;
    int full = (out_size >= FULLN) ? 1 : 0;

    cudaFuncSetAttribute(enc_k, cudaFuncAttributeMaxDynamicSharedMemorySize, ENC_F * 4);
    cudaFuncSetAttribute(dec_k, cudaFuncAttributeMaxDynamicSharedMemorySize, DEC_F * 4);

    enc_k<<<128, 128, ENC_F * 4>>>(tokens, emb, eWih0, eWhh0, ebih0, ebhh0,
                                   eWih1, eWhh1, ebih1, ebhh1,
                                   muW, mub, varW, varb, prjW, prjb, out, full);
    dec_k<<<128, 128, DEC_F * 4>>>(demb, dWih0, dWhh0, dbih0, dbhh0,
                                   dWih1, dWhh1, dbih1, dbhh1, headW, headb, out);
    if (full)
        tok_cast_k<<<(BBATCH * SSEQ + 255) / 256, 256>>>(tokens, out + TOKOFF);
}

// round 16
// speedup vs baseline: 1.2269x; 1.0001x over previous
#include <cuda_runtime.h>
#include <cstdint>

typedef unsigned int u32;
typedef unsigned long long u64;

#define BBATCH 2048
#define SSEQ 256
#define NTOK 6
#define STARTTOK 4

#define RECONS_N (BBATCH*SSEQ*4)
#define TOKOFF RECONS_N
#define MUOFF (RECONS_N + BBATCH*SSEQ)
#define LVOFF (MUOFF + BBATCH*3)
#define FULLN (LVOFF + BBATCH*3)

// common SMEM float offsets
#define O_W1A 0        /* [d][u][4] = wir,whr,wiz,whz : 16384 */
#define O_W1B 16384    /* [d][u][2] = win,whn : 8192 */
#define O_W0A 24576    /* [d][u][4] = whr,whz,whn,pad : 16384 */
#define O_TAB 40960    /* 6*192 */
#define O_B0  42112
#define O_BI1 42304
#define O_BH1 42496
#define O_H0B 42688    /* [2][64][20] : 2560 */
#define O_H1B 45248    /* [2][64][20] : 2560 */
// encoder-only
#define O_MUW 47808
#define O_VARW 48000
#define O_MUB 48192
#define O_VARB 48196
#define O_PRJW 48200
#define O_PRJB 48392
#define O_ZS  48456
#define O_TOKS 48504   /* 4096 ints */
#define ENC_F 52600
// decoder-only
#define O_HW  47808    /* 256 */
#define O_HB2 48064    /* 4 */
#define O_K0  48068    /* 256 */
#define O_K1  48324    /* 256 */
#define O_TOKD 48580   /* 16 ints */
#define O_LSTG 48596   /* [4w*4v][16rows] = 256 */
#define DEC_F 48852

__device__ float g_hz[BBATCH*64];

// ---------- f32x2 helpers ----------
__device__ __forceinline__ void upk2(u64 v, float& a, float& b){
    asm("mov.b64 {%0,%1},%2;" : "=f"(a), "=f"(b) : "l"(v));
}
__device__ __forceinline__ u64 pack2(float x, float y){
    u64 r; asm("mov.b64 %0,{%1,%2};" : "=l"(r) : "f"(x), "f"(y)); return r;
}
__device__ __forceinline__ u64 dupf(float f){ return pack2(f, f); }
__device__ __forceinline__ u64 ff2(u64 a, u64 b, u64 c){
    u64 d; asm("fma.rn.f32x2 %0,%1,%2,%3;" : "=l"(d) : "l"(a), "l"(b), "l"(c)); return d;
}
__device__ __forceinline__ u64 add2(u64 a, u64 b){
    u64 c; asm("add.rn.f32x2 %0,%1,%2;" : "=l"(c) : "l"(a), "l"(b)); return c;
}
__device__ __forceinline__ u64 d2u(double d){ return (u64)__double_as_longlong(d); }

// ---------- threefry2x32-20 (exact JAX) ----------
__device__ __forceinline__ void threefry(u32 k0, u32 k1, u32 x0, u32 x1, u32& o0, u32& o1){
    u32 ks2 = k0 ^ k1 ^ 0x1BD11BDAu;
    x0 += k0; x1 += k1;
#define TFR(r) { x0 += x1; x1 = __funnelshift_l(x1, x1, (r)); x1 ^= x0; }
    TFR(13) TFR(15) TFR(26) TFR(6)   x0 += k1;  x1 += ks2 + 1u;
    TFR(17) TFR(29) TFR(16) TFR(24)  x0 += ks2; x1 += k0 + 2u;
    TFR(13) TFR(15) TFR(26) TFR(6)   x0 += k0;  x1 += k1 + 3u;
    TFR(17) TFR(29) TFR(16) TFR(24)  x0 += k1;  x1 += ks2 + 4u;
    TFR(13) TFR(15) TFR(26) TFR(6)   x0 += ks2; x1 += k0 + 5u;
#undef TFR
    o0 = x0; o1 = x1;
}
__device__ __forceinline__ u32 tf_bits32(u32 k0, u32 k1, u32 i){
    u32 a, b; threefry(k0, k1, 0u, i, a, b); return a ^ b;
}
__device__ __forceinline__ float bits2f(u32 b){
    return __uint_as_float((b >> 9) | 0x3f800000u) - 1.0f;
}
__device__ __forceinline__ float sigf(float x){ return 0.5f + 0.5f * tanhf(0.5f * x); }

__device__ __forceinline__ float erfinv_f(float x){
    float w = -log1pf(-x * x), p;
    if (w < 5.f){
        w -= 2.5f;
        p = 2.81022636e-08f;
        p = fmaf(p, w, 3.43273939e-07f);
        p = fmaf(p, w, -3.5233877e-06f);
        p = fmaf(p, w, -4.39150654e-06f);
        p = fmaf(p, w, 0.00021858087f);
        p = fmaf(p, w, -0.00125372503f);
        p = fmaf(p, w, -0.00417768164f);
        p = fmaf(p, w, 0.246640727f);
        p = fmaf(p, w, 1.50140941f);
    } else {
        w = sqrtf(w) - 3.f;
        p = -0.000200214257f;
        p = fmaf(p, w, 0.000100950558f);
        p = fmaf(p, w, 0.00134934322f);
        p = fmaf(p, w, -0.00367342844f);
        p = fmaf(p, w, 0.00573950773f);
        p = fmaf(p, w, -0.0076224613f);
        p = fmaf(p, w, 0.00943887047f);
        p = fmaf(p, w, 1.00167406f);
        p = fmaf(p, w, 2.83297682f);
    }
    return p * x;
}

// ---------- plain l0 matvec (decoder prologue only) ----------
__device__ __forceinline__ void l0mv(const float* h0c, const float* w0,
                                     u64* ar, u64* az, u64* an){
#pragma unroll
    for (int k = 0; k < 4; k++){ ar[k] = az[k] = an[k] = 0ull; }
#pragma unroll 4
    for (int d = 0; d < 64; d++){
        float4 w = *(const float4*)(w0 + d * 256);
        u64 WR = dupf(w.x), WZ = dupf(w.y), WN = dupf(w.z);
        double2 A = *(const double2*)(h0c + d * 20);
        double2 B = *(const double2*)(h0c + d * 20 + 4);
        u64 h[4] = { d2u(A.x), d2u(A.y), d2u(B.x), d2u(B.y) };
#pragma unroll
        for (int k = 0; k < 4; k++){
            ar[k] = ff2(h[k], WR, ar[k]);
            az[k] = ff2(h[k], WZ, az[k]);
            an[k] = ff2(h[k], WN, an[k]);
        }
    }
}

// ---------- FUSED matvec: l1mv(step s) + l0mv(step s+1) ----------
// xc = h0_new(s) (input to l1 AND input to next step's l0); hc = h1(s-1).
__device__ __forceinline__ void fused_mv(const float* xc, const float* hc,
                                         const float* w1a, const float* w1b,
                                         const float* w0,
                                         u64 pr[4], u64 pz[4], u64 pin[4], u64 phn[4],
                                         u64 ar[4], u64 az[4], u64 an[4]){
#pragma unroll
    for (int k = 0; k < 4; k++){
        pr[k]=pz[k]=pin[k]=phn[k]=0ull;
        ar[k]=az[k]=an[k]=0ull;
    }
#pragma unroll 4
    for (int d = 0; d < 64; d++){
        float4 wa = *(const float4*)(w1a + d * 256);
        float2 wb = *(const float2*)(w1b + d * 128);
        float4 w0v = *(const float4*)(w0 + d * 256);
        u64 WIR = dupf(wa.x), WHR = dupf(wa.y);
        u64 WIZ = dupf(wa.z), WHZ = dupf(wa.w);
        u64 WIN = dupf(wb.x), WHN = dupf(wb.y);
        u64 W0R = dupf(w0v.x), W0Z = dupf(w0v.y), W0N = dupf(w0v.z);
        double2 XA = *(const double2*)(xc + d * 20);
        double2 XB = *(const double2*)(xc + d * 20 + 4);
        double2 HA = *(const double2*)(hc + d * 20);
        double2 HB = *(const double2*)(hc + d * 20 + 4);
        u64 x[4] = { d2u(XA.x), d2u(XA.y), d2u(XB.x), d2u(XB.y) };
        u64 h[4] = { d2u(HA.x), d2u(HA.y), d2u(HB.x), d2u(HB.y) };
#pragma unroll
        for (int k = 0; k < 4; k++){
            pr[k]  = ff2(x[k], WIR, ff2(h[k], WHR, pr[k]));
            pz[k]  = ff2(x[k], WIZ, ff2(h[k], WHZ, pz[k]));
            pin[k] = ff2(x[k], WIN, pin[k]);
            phn[k] = ff2(h[k], WHN, phn[k]);
            ar[k]  = ff2(x[k], W0R, ar[k]);
            az[k]  = ff2(x[k], W0Z, az[k]);
            an[k]  = ff2(x[k], W0N, an[k]);
        }
    }
}

// L0 epilogue: tk[8] = tokens for rows 8rg..8rg+7; writes h0 pairs to h0n (+2k)
__device__ __forceinline__ void l0epi(const float* sm, float* h0n, int ug,
                                      const int* tk, const u64* ar, const u64* az,
                                      const u64* an, float b0r, float b0z, float b0n,
                                      float* hp0x, float* hp0y){
#pragma unroll
    for (int k = 0; k < 4; k++){
        const float* tb0 = sm + O_TAB + tk[2*k] * 192 + ug;
        const float* tb1 = sm + O_TAB + tk[2*k+1] * 192 + ug;
        float arx, ary, azx, azy, anx, any;
        upk2(ar[k], arx, ary); upk2(az[k], azx, azy); upk2(an[k], anx, any);
        float rx = sigf(tb0[0] + arx + b0r);
        float ry = sigf(tb1[0] + ary + b0r);
        float zx = sigf(tb0[64] + azx + b0z);
        float zy = sigf(tb1[64] + azy + b0z);
        float nx = tanhf(tb0[128] + rx * (anx + b0n));
        float ny = tanhf(tb1[128] + ry * (any + b0n));
        float hx = (1.f - zx) * nx + zx * hp0x[k];
        float hy = (1.f - zy) * ny + zy * hp0y[k];
        hp0x[k] = hx; hp0y[k] = hy;
        *(float2*)(h0n + 2 * k) = make_float2(hx, hy);
    }
}

__device__ __forceinline__ void l1epi(float* h1n, const u64* pr, const u64* pz,
                                      const u64* pin, const u64* phn,
                                      float bi1r, float bi1z, float bi1n,
                                      float bh1r, float bh1z, float bh1n,
                                      float* hp1x, float* hp1y){
#pragma unroll
    for (int k = 0; k < 4; k++){
        float prx, pry, pzx, pzy, pix, piy, phx, phy;
        upk2(pr[k], prx, pry); upk2(pz[k], pzx, pzy);
        upk2(pin[k], pix, piy); upk2(phn[k], phx, phy);
        float rx = sigf(prx + bi1r + bh1r);
        float ry = sigf(pry + bi1r + bh1r);
        float zx = sigf(pzx + bi1z + bh1z);
        float zy = sigf(pzy + bi1z + bh1z);
        float nx = tanhf(pix + bi1n + rx * (phx + bh1n));
        float ny = tanhf(piy + bi1n + ry * (phy + bh1n));
        float hx = (1.f - zx) * nx + zx * hp1x[k];
        float hy = (1.f - zy) * ny + zy * hp1y[k];
        hp1x[k] = hx; hp1y[k] = hy;
        *(float2*)(h1n + 2 * k) = make_float2(hx, hy);
    }
}

// ---------- weight staging ----------
__device__ __forceinline__ void stage_weights(float* sm, int tid,
    const float* Whh0, const float* Wih1, const float* Whh1,
    const float* bhh0, const float* bih1, const float* bhh1){
    for (int i = tid; i < 4096; i += 128){
        int u = i >> 6, d = i & 63;
        int o = (d * 64 + u);
        sm[O_W1A + o*4 + 0] = Wih1[u*64 + d];
        sm[O_W1A + o*4 + 1] = Whh1[u*64 + d];
        sm[O_W1A + o*4 + 2] = Wih1[(64+u)*64 + d];
        sm[O_W1A + o*4 + 3] = Whh1[(64+u)*64 + d];
        sm[O_W1B + o*2 + 0] = Wih1[(128+u)*64 + d];
        sm[O_W1B + o*2 + 1] = Whh1[(128+u)*64 + d];
        sm[O_W0A + o*4 + 0] = Whh0[u*64 + d];
        sm[O_W0A + o*4 + 1] = Whh0[(64+u)*64 + d];
        sm[O_W0A + o*4 + 2] = Whh0[(128+u)*64 + d];
        sm[O_W0A + o*4 + 3] = 0.f;
    }
    for (int i = tid; i < 192; i += 128){
        sm[O_B0 + i] = bhh0[i];
        sm[O_BI1 + i] = bih1[i];
        sm[O_BH1 + i] = bhh1[i];
    }
}

// =========================== ENCODER ===========================
__global__ void __launch_bounds__(128, 1) enc_k(
    const int* __restrict__ tokens, const float* __restrict__ emb,
    const float* __restrict__ Wih0, const float* __restrict__ Whh0,
    const float* __restrict__ bih0, const float* __restrict__ bhh0,
    const float* __restrict__ Wih1, const float* __restrict__ Whh1,
    const float* __restrict__ bih1, const float* __restrict__ bhh1,
    const float* __restrict__ muW, const float* __restrict__ mub,
    const float* __restrict__ varW, const float* __restrict__ varb,
    const float* __restrict__ prjW, const float* __restrict__ prjb,
    float* __restrict__ out, int wr_extra)
{
    extern __shared__ float sm[];
    int tid = threadIdx.x;
    stage_weights(sm, tid, Whh0, Wih1, Whh1, bhh0, bih1, bhh1);
    for (int i = tid; i < NTOK * 192; i += 128){
        int t = i / 192, u = i % 192;
        float s = bih0[u];
#pragma unroll
        for (int e = 0; e < 8; e++) s = fmaf(emb[t * 8 + e], Wih0[u * 8 + e], s);
        sm[O_TAB + i] = s;
    }
    for (int i = tid; i < 192; i += 128){
        sm[O_MUW + i] = muW[i]; sm[O_VARW + i] = varW[i]; sm[O_PRJW + i] = prjW[i];
    }
    if (tid < 3){ sm[O_MUB + tid] = mub[tid]; sm[O_VARB + tid] = varb[tid]; }
    for (int i = tid; i < 64; i += 128) sm[O_PRJB + i] = prjb[i];
    int base = blockIdx.x * 16;
    int* toksS = (int*)(sm + O_TOKS);
    for (int i = tid; i < 16 * 256; i += 128) toksS[i] = tokens[base * 256 + i];
    for (int i = tid; i < 1280; i += 128){ sm[O_H0B + i] = 0.f; sm[O_H1B + i] = 0.f; }
    __syncthreads();

    int warp = tid >> 5, lane = tid & 31;
    int ul = lane & 15, rg = lane >> 4;
    int ug = warp * 16 + ul;
    const float* w0  = sm + O_W0A + ug * 4;
    const float* w1a = sm + O_W1A + ug * 4;
    const float* w1b = sm + O_W1B + ug * 2;
    float b0r = sm[O_B0 + ug],  b0z = sm[O_B0 + 64 + ug],  b0n = sm[O_B0 + 128 + ug];
    float i1r = sm[O_BI1 + ug], i1z = sm[O_BI1 + 64 + ug], i1n = sm[O_BI1 + 128 + ug];
    float h1r = sm[O_BH1 + ug], h1z = sm[O_BH1 + 64 + ug], h1n = sm[O_BH1 + 128 + ug];

    float hp0x[4], hp0y[4], hp1x[4], hp1y[4];
#pragma unroll
    for (int k = 0; k < 4; k++){ hp0x[k] = hp0y[k] = hp1x[k] = hp1y[k] = 0.f; }

    // h0_init = 0 -> l0 matvec of step 0 is exactly 0
    u64 arC[4] = {0,0,0,0}, azC[4] = {0,0,0,0}, anC[4] = {0,0,0,0};

    for (int s = 0; s < 256; s++){
        int cb = s & 1, nb = cb ^ 1;
        int tk[8];
#pragma unroll
        for (int r = 0; r < 8; r++) tk[r] = toksS[(8 * rg + r) * 256 + s];
        l0epi(sm, sm + O_H0B + nb * 1280 + ug * 20 + 8 * rg, ug, tk,
              arC, azC, anC, b0r, b0z, b0n, hp0x, hp0y);
        __syncthreads();
        u64 pr[4], pz[4], pin[4], phn[4];
        fused_mv(sm + O_H0B + nb * 1280 + rg * 8, sm + O_H1B + cb * 1280 + rg * 8,
                 w1a, w1b, w0, pr, pz, pin, phn, arC, azC, anC);
        l1epi(sm + O_H1B + nb * 1280 + ug * 20 + 8 * rg, pr, pz, pin, phn,
              i1r, i1z, i1n, h1r, h1z, h1n, hp1x, hp1y);
    }
    __syncthreads();

    // final h1 in h1b buffer 0
    if (lane < 12){
        int r = lane / 3, j = lane % 3;
        int lr = warp * 4 + r;
        int row = base + lr;
        float m = sm[O_MUB + j], v = sm[O_VARB + j];
        for (int d = 0; d < 64; d++){
            float h = sm[O_H1B + d * 20 + lr];
            m = fmaf(h, sm[O_MUW + j * 64 + d], m);
            v = fmaf(h, sm[O_VARW + j * 64 + d], v);
        }
        u32 bits = tf_bits32(0u, 1u, (u32)(row * 3 + j));
        float f01 = bits2f(bits);
        const float LO = -0.99999994f;
        float u = fmaxf(LO, fmaf(f01, 2.0f, LO));
        float eps = 1.41421356f * erfinv_f(u);
        float z = fmaf(eps, expf(0.5f * v), m);
        sm[O_ZS + lr * 3 + j] = z;
        if (wr_extra){ out[MUOFF + row * 3 + j] = m; out[LVOFF + row * 3 + j] = v; }
    }
    __syncthreads();
    for (int i = tid; i < 1024; i += 128){
        int r = i >> 6, d = i & 63;
        float z0 = sm[O_ZS + r * 3];
        float z1 = sm[O_ZS + r * 3 + 1];
        float z2 = sm[O_ZS + r * 3 + 2];
        float hx = sm[O_PRJB + d] + z0 * sm[O_PRJW + d * 3] + z1 * sm[O_PRJW + d * 3 + 1]
                 + z2 * sm[O_PRJW + d * 3 + 2];
        g_hz[(base + r) * 64 + d] = hx;
    }
}

// =========================== DECODER ===========================
__global__ void __launch_bounds__(128, 1) dec_k(
    const float* __restrict__ dec_emb,
    const float* __restrict__ Wih0, const float* __restrict__ Whh0,
    const float* __restrict__ bih0, const float* __restrict__ bhh0,
    const float* __restrict__ Wih1, const float* __restrict__ Whh1,
    const float* __restrict__ bih1, const float* __restrict__ bhh1,
    const float* __restrict__ headW, const float* __restrict__ headb,
    float* __restrict__ out)
{
    extern __shared__ float sm[];
    int tid = threadIdx.x;
    stage_weights(sm, tid, Whh0, Wih1, Whh1, bhh0, bih1, bhh1);
    for (int i = tid; i < NTOK * 192; i += 128){
        int t = i / 192, u = i % 192;
        float s = bih0[u];
        for (int d = 0; d < 64; d++) s = fmaf(dec_emb[t * 64 + d], Wih0[u * 64 + d], s);
        sm[O_TAB + i] = s;
    }
    for (int i = tid; i < 256; i += 128) sm[O_HW + i] = headW[i];
    if (tid < 4) sm[O_HB2 + tid] = headb[tid];
    u32* K0 = (u32*)(sm + O_K0);
    u32* K1 = (u32*)(sm + O_K1);
    for (int i = tid; i < 256; i += 128){
        u32 a, b; threefry(0u, 2u, 0u, (u32)i, a, b);
        K0[i] = a; K1[i] = b;
    }
    int* tokD = (int*)(sm + O_TOKD);
    if (tid < 16) tokD[tid] = STARTTOK;
    int base = blockIdx.x * 16;
    for (int i = tid; i < 1024; i += 128){
        int r = i >> 6, d = i & 63;
        float v = g_hz[(base + r) * 64 + d];
        sm[O_H0B + d * 20 + r] = v;
        sm[O_H1B + d * 20 + r] = v;
    }
    __syncthreads();

    int warp = tid >> 5, lane = tid & 31;
    int ul = lane & 15, rg = lane >> 4;
    int ug = warp * 16 + ul;
    const float* w0  = sm + O_W0A + ug * 4;
    const float* w1a = sm + O_W1A + ug * 4;
    const float* w1b = sm + O_W1B + ug * 2;
    float b0r = sm[O_B0 + ug],  b0z = sm[O_B0 + 64 + ug],  b0n = sm[O_B0 + 128 + ug];
    float i1r = sm[O_BI1 + ug], i1z = sm[O_BI1 + 64 + ug], i1n = sm[O_BI1 + 128 + ug];
    float h1r = sm[O_BH1 + ug], h1z = sm[O_BH1 + 64 + ug], h1n = sm[O_BH1 + 128 + ug];
    u64 WV[4];
#pragma unroll
    for (int v = 0; v < 4; v++) WV[v] = dupf(sm[O_HW + v * 64 + ug]);

    float hp0x[4], hp0y[4], hp1x[4], hp1y[4];
#pragma unroll
    for (int k = 0; k < 4; k++){
        float2 h = *(const float2*)(sm + O_H0B + ug * 20 + 8 * rg + 2 * k);
        hp0x[k] = hp1x[k] = h.x;
        hp0y[k] = hp1y[k] = h.y;
    }

    // prologue: l0 matvec for step 0 on h0 = hz (buffer 0)
    u64 arC[4], azC[4], anC[4];
    l0mv(sm + O_H0B + rg * 8, w0, arC, azC, anC);

    const float TINYF = 1.17549435e-38f;
    for (int s = 0; s < 256; s++){
        int cb = s & 1, nb = cb ^ 1;
        int tk[8];
#pragma unroll
        for (int r = 0; r < 8; r++) tk[r] = tokD[8 * rg + r];
        l0epi(sm, sm + O_H0B + nb * 1280 + ug * 20 + 8 * rg, ug, tk,
              arC, azC, anC, b0r, b0z, b0n, hp0x, hp0y);
        __syncthreads();   // SYNC_B: new h0 visible
        u64 pr[4], pz[4], pin[4], phn[4];
        fused_mv(sm + O_H0B + nb * 1280 + rg * 8, sm + O_H1B + cb * 1280 + rg * 8,
                 w1a, w1b, w0, pr, pz, pin, phn, arC, azC, anC);
        l1epi(sm + O_H1B + nb * 1280 + ug * 20 + 8 * rg, pr, pz, pin, phn,
              i1r, i1z, i1n, h1r, h1z, h1n, hp1x, hp1y);

        // head partials per (pair, v), reduce over this warp's 16 units
        u64 pp[16];
#pragma unroll
        for (int k = 0; k < 4; k++){
            u64 hp = pack2(hp1x[k], hp1y[k]);
#pragma unroll
            for (int v = 0; v < 4; v++) pp[k * 4 + v] = ff2(hp, WV[v], 0ull);
        }
#pragma unroll
        for (int m = 1; m < 16; m <<= 1){
#pragma unroll
            for (int j = 0; j < 16; j++){
                double o = __shfl_xor_sync(0xffffffffu, __longlong_as_double((long long)pp[j]), m);
                pp[j] = add2(pp[j], d2u(o));
            }
        }
        if (ul == 0){
#pragma unroll
            for (int k = 0; k < 4; k++)
#pragma unroll
                for (int v = 0; v < 4; v++){
                    float a, b; upk2(pp[k * 4 + v], a, b);
                    *(float2*)(sm + O_LSTG + (warp * 4 + v) * 16 + 8 * rg + 2 * k)
                        = make_float2(a, b);
                }
        }
        __syncthreads();   // SYNC_C: LSTG + h1 + token ordering for next step

        // sample: warp handles its 4 rows
        {
            int k = lane & 15, r = k >> 2, v = k & 3;
            int lr = warp * 4 + r;
            int row = base + lr;
            float sum = ((sm[O_LSTG + v * 16 + lr] + sm[O_LSTG + (4 + v) * 16 + lr])
                         + sm[O_LSTG + (8 + v) * 16 + lr]) + sm[O_LSTG + (12 + v) * 16 + lr];
            float logit = sum + sm[O_HB2 + v];
            u32 bits = tf_bits32(K0[s], K1[s], (u32)(row * 4 + v));
            float f01 = bits2f(bits);
            float u = fmaxf(TINYF, f01 + TINYF);
            float g = -logf(-logf(u));
            float y = logit + g;
            float mx = logit;
            mx = fmaxf(mx, __shfl_xor_sync(0xffffffffu, mx, 1));
            mx = fmaxf(mx, __shfl_xor_sync(0xffffffffu, mx, 2));
            float e = expf(logit - mx);
            float den = e;
            den += __shfl_xor_sync(0xffffffffu, den, 1);
            den += __shfl_xor_sync(0xffffffffu, den, 2);
            if (lane < 16) out[((size_t)row * 256 + s) * 4 + v] = e / den;
            float by = y; int bi = v;
            { float oy = __shfl_xor_sync(0xffffffffu, by, 1);
              int   oi = __shfl_xor_sync(0xffffffffu, bi, 1);
              if (oy > by || (oy == by && oi < bi)){ by = oy; bi = oi; } }
            { float oy = __shfl_xor_sync(0xffffffffu, by, 2);
              int   oi = __shfl_xor_sync(0xffffffffu, bi, 2);
              if (oy > by || (oy == by && oi < bi)){ by = oy; bi = oi; } }
            if (lane < 16 && v == 0) tokD[lr] = bi;
        }
        __syncthreads();   // SYNC_A for next step: tokD writes visible before l0epi(s+1)
    }
}

__global__ void tok_cast_k(const int* __restrict__ tokens, float* __restrict__ dst){
    int i = blockIdx.x * blockDim.x + threadIdx.x;
    if (i < BBATCH * SSEQ) dst[i] = (float)tokens[i];
}

extern "C" void kernel_launch(void* const* d_in, const int* in_sizes, int n_in,
                              void* d_out, int out_size){
    const int*   tokens = (const int*)  d_in[0];
    const float* emb    = (const float*)d_in[1];
    const float* eWih0  = (const float*)d_in[2];
    const float* eWhh0  = (const float*)d_in[3];
    const float* ebih0  = (const float*)d_in[4];
    const float* ebhh0  = (const float*)d_in[5];
    const float* eWih1  = (const float*)d_in[6];
    const float* eWhh1  = (const float*)d_in[7];
    const float* ebih1  = (const float*)d_in[8];
    const float* ebhh1  = (const float*)d_in[9];
    const float* muW    = (const float*)d_in[10];
    const float* mub    = (const float*)d_in[11];
    const float* varW   = (const float*)d_in[12];
    const float* varb   = (const float*)d_in[13];
    const float* demb   = (const float*)d_in[14];
    const float* prjW   = (const float*)d_in[15];
    const float* prjb   = (const float*)d_in[16];
    const float* dWih0  = (const float*)d_in[17];
    const float* dWhh0  = (const float*)d_in[18];
    const float* dbih0  = (const float*)d_in[19];
    const float* dbhh0  = (const float*)d_in[20];
    const float* dWih1  = (const float*)d_in[21];
    const float* dWhh1  = (const float*)d_in[22];
    const float* dbih1  = (const float*)d_in[23];
    const float* dbhh1  = (const float*)d_in[24];
    const float* headW  = (const float*)d_in[25];
    const float* headb  = (const float*)d_in[26];
    float* out = (float*)d_out;
    int full = (out_size >= FULLN) ? 1 : 0;

    cudaFuncSetAttribute(enc_k, cudaFuncAttributeMaxDynamicSharedMemorySize, ENC_F * 4);
    cudaFuncSetAttribute(dec_k, cudaFuncAttributeMaxDynamicSharedMemorySize, DEC_F * 4);

    enc_k<<<128, 128, ENC_F * 4>>>(tokens, emb, eWih0, eWhh0, ebih0, ebhh0,
                                   eWih1, eWhh1, ebih1, ebhh1,
                                   muW, mub, varW, varb, prjW, prjb, out, full);
    dec_k<<<128, 128, DEC_F * 4>>>(demb, dWih0, dWhh0, dbih0, dbhh0,
                                   dWih1, dWhh1, dbih1, dbhh1, headW, headb, out);
    if (full)
        tok_cast_k<<<(BBATCH * SSEQ + 255) / 256, 256>>>(tokens, out + TOKOFF);
}